// round 1
// baseline (speedup 1.0000x reference)
#include <cuda_runtime.h>
#include <cstddef>

// Problem constants (fixed shapes per reference)
#define EMBED  4096   // in_features == K
#define RPT    1024   // rows per tile
#define NTILES 4
#define OUTF   4096   // out_features

// Decoded weight scratch: [OUTF, EMBED] fp32 row-major = 64 MB (static device global,
// allowed under the allocation rules).
__device__ float g_W[(size_t)OUTF * EMBED];

// Tiling config
#define BM 128
#define BN 128
#define BK 16
#define TM 8
#define TN 8
#define NTHREADS 256
#define APAD 4   // shared row padding (floats); keeps float4 alignment (132*4 % 16 == 0)

// ---------------------------------------------------------------------------
// Detect whether the indices buffer is int64 (little-endian) or int32.
// Values are in [0, 16384), so for int64 every high 32-bit word is zero.
// 8 consecutive zero odd-words from random int32 indices: prob ~ (1/16384)^8.
// ---------------------------------------------------------------------------
__device__ __forceinline__ bool indices_are_i64(const int* __restrict__ p) {
    bool is64 = true;
#pragma unroll
    for (int i = 0; i < 8; ++i) is64 = is64 && (p[2 * i + 1] == 0);
    return is64;
}

// ---------------------------------------------------------------------------
// Kernel 1: decode weight.
//   For tile t: W[t*RPT + r, e] = scales[t] * sum_d codewords[idx[t,r], d] * R_t[d, e]
// GEMM form C = A @ B, A = gathered codewords [RPT, EMBED] (K-contiguous),
// B = R_t [EMBED, EMBED] (N-contiguous).
// ---------------------------------------------------------------------------
__global__ __launch_bounds__(NTHREADS, 2)
void decode_kernel(const float* __restrict__ codewords,
                   const int*   __restrict__ idx_raw,
                   const float* __restrict__ rot,
                   const float* __restrict__ scales)
{
    __shared__ float As[BK][BM + APAD];
    __shared__ float Bs[BK][BN + APAD];

    const int t   = blockIdx.z;
    const int bm  = blockIdx.y * BM;
    const int bn  = blockIdx.x * BN;
    const int tid = threadIdx.x;
    const int ty  = tid >> 4;      // 0..15
    const int tx  = tid & 15;      // 0..15

    const bool is64 = indices_are_i64(idx_raw);

    // A-tile loader mapping: thread handles rows (tid>>2) and (tid>>2)+64,
    // quad q = tid&3 of each 16-float row slice.
    const int arow0 = (tid >> 2);       // 0..63
    const int arow1 = arow0 + 64;       // 64..127
    const int q     = (tid & 3);

    const int grow0 = t * RPT + bm + arow0;
    const int grow1 = t * RPT + bm + arow1;
    const int cidx0 = is64 ? idx_raw[2 * grow0] : idx_raw[grow0];
    const int cidx1 = is64 ? idx_raw[2 * grow1] : idx_raw[grow1];

    const float* __restrict__ aptr0 = codewords + (size_t)cidx0 * EMBED + q * 4;
    const float* __restrict__ aptr1 = codewords + (size_t)cidx1 * EMBED + q * 4;

    // B-tile loader mapping: f = tid + i*256 ; k = f>>5 ; n4 = (f&31)*4
    const float* __restrict__ rotT = rot + (size_t)t * EMBED * EMBED;

    float acc[TM][TN];
#pragma unroll
    for (int i = 0; i < TM; ++i)
#pragma unroll
        for (int j = 0; j < TN; ++j) acc[i][j] = 0.0f;

    for (int k0 = 0; k0 < EMBED; k0 += BK) {
        // --- load A (gathered codewords), transpose into As[k][m] ---
        {
            float4 v0 = *reinterpret_cast<const float4*>(aptr0 + k0);
            float4 v1 = *reinterpret_cast<const float4*>(aptr1 + k0);
            As[q * 4 + 0][arow0] = v0.x;
            As[q * 4 + 1][arow0] = v0.y;
            As[q * 4 + 2][arow0] = v0.z;
            As[q * 4 + 3][arow0] = v0.w;
            As[q * 4 + 0][arow1] = v1.x;
            As[q * 4 + 1][arow1] = v1.y;
            As[q * 4 + 2][arow1] = v1.z;
            As[q * 4 + 3][arow1] = v1.w;
        }
        // --- load B (rotation rows), direct into Bs[k][n] ---
#pragma unroll
        for (int i = 0; i < 2; ++i) {
            int f  = tid + i * NTHREADS;
            int k  = f >> 5;            // 0..15
            int n4 = (f & 31) * 4;      // 0..124
            float4 v = *reinterpret_cast<const float4*>(
                rotT + (size_t)(k0 + k) * EMBED + bn + n4);
            *reinterpret_cast<float4*>(&Bs[k][n4]) = v;
        }
        __syncthreads();

#pragma unroll
        for (int k = 0; k < BK; ++k) {
            float a[TM], b[TN];
#pragma unroll
            for (int i = 0; i < TM; ++i) a[i] = As[k][ty * TM + i];
#pragma unroll
            for (int j = 0; j < TN; ++j) b[j] = Bs[k][tx * TN + j];
#pragma unroll
            for (int i = 0; i < TM; ++i)
#pragma unroll
                for (int j = 0; j < TN; ++j) acc[i][j] += a[i] * b[j];
        }
        __syncthreads();
    }

    const float s = scales[t];
#pragma unroll
    for (int i = 0; i < TM; ++i) {
        size_t o = (size_t)(t * RPT + bm + ty * TM + i) * EMBED + bn + tx * TN;
#pragma unroll
        for (int j = 0; j < TN; j += 4) {
            float4 v = make_float4(acc[i][j + 0] * s, acc[i][j + 1] * s,
                                   acc[i][j + 2] * s, acc[i][j + 3] * s);
            *reinterpret_cast<float4*>(&g_W[o + j]) = v;
        }
    }
}

// ---------------------------------------------------------------------------
// Kernel 2: y = x @ W^T + bias.
// C = A @ B^T, A = x [M, EMBED] row-major, B = W [OUTF, EMBED] row-major.
// Both operands K-contiguous -> both use the transpose-load pattern.
// ---------------------------------------------------------------------------
__global__ __launch_bounds__(NTHREADS, 2)
void linear_kernel(const float* __restrict__ x,
                   const float* __restrict__ bias,
                   float*       __restrict__ out)
{
    __shared__ float As[BK][BM + APAD];
    __shared__ float Bs[BK][BN + APAD];

    const int bm  = blockIdx.y * BM;
    const int bn  = blockIdx.x * BN;
    const int tid = threadIdx.x;
    const int ty  = tid >> 4;
    const int tx  = tid & 15;

    const int row0 = (tid >> 2);   // 0..63
    const int row1 = row0 + 64;
    const int q    = (tid & 3);

    const float* __restrict__ aptr0 = x + (size_t)(bm + row0) * EMBED + q * 4;
    const float* __restrict__ aptr1 = x + (size_t)(bm + row1) * EMBED + q * 4;
    const float* __restrict__ bptr0 = g_W + (size_t)(bn + row0) * EMBED + q * 4;
    const float* __restrict__ bptr1 = g_W + (size_t)(bn + row1) * EMBED + q * 4;

    float acc[TM][TN];
#pragma unroll
    for (int i = 0; i < TM; ++i)
#pragma unroll
        for (int j = 0; j < TN; ++j) acc[i][j] = 0.0f;

    for (int k0 = 0; k0 < EMBED; k0 += BK) {
        {
            float4 va0 = *reinterpret_cast<const float4*>(aptr0 + k0);
            float4 va1 = *reinterpret_cast<const float4*>(aptr1 + k0);
            float4 vb0 = *reinterpret_cast<const float4*>(bptr0 + k0);
            float4 vb1 = *reinterpret_cast<const float4*>(bptr1 + k0);
            As[q * 4 + 0][row0] = va0.x;
            As[q * 4 + 1][row0] = va0.y;
            As[q * 4 + 2][row0] = va0.z;
            As[q * 4 + 3][row0] = va0.w;
            As[q * 4 + 0][row1] = va1.x;
            As[q * 4 + 1][row1] = va1.y;
            As[q * 4 + 2][row1] = va1.z;
            As[q * 4 + 3][row1] = va1.w;
            Bs[q * 4 + 0][row0] = vb0.x;
            Bs[q * 4 + 1][row0] = vb0.y;
            Bs[q * 4 + 2][row0] = vb0.z;
            Bs[q * 4 + 3][row0] = vb0.w;
            Bs[q * 4 + 0][row1] = vb1.x;
            Bs[q * 4 + 1][row1] = vb1.y;
            Bs[q * 4 + 2][row1] = vb1.z;
            Bs[q * 4 + 3][row1] = vb1.w;
        }
        __syncthreads();

#pragma unroll
        for (int k = 0; k < BK; ++k) {
            float a[TM], b[TN];
#pragma unroll
            for (int i = 0; i < TM; ++i) a[i] = As[k][ty * TM + i];
#pragma unroll
            for (int j = 0; j < TN; ++j) b[j] = Bs[k][tx * TN + j];
#pragma unroll
            for (int i = 0; i < TM; ++i)
#pragma unroll
                for (int j = 0; j < TN; ++j) acc[i][j] += a[i] * b[j];
        }
        __syncthreads();
    }

    float bvals[TN];
#pragma unroll
    for (int j = 0; j < TN; ++j) bvals[j] = bias[bn + tx * TN + j];

#pragma unroll
    for (int i = 0; i < TM; ++i) {
        size_t o = (size_t)(bm + ty * TM + i) * OUTF + bn + tx * TN;
#pragma unroll
        for (int j = 0; j < TN; j += 4) {
            float4 v = make_float4(acc[i][j + 0] + bvals[j + 0],
                                   acc[i][j + 1] + bvals[j + 1],
                                   acc[i][j + 2] + bvals[j + 2],
                                   acc[i][j + 3] + bvals[j + 3]);
            *reinterpret_cast<float4*>(&out[o + j]) = v;
        }
    }
}

// ---------------------------------------------------------------------------
// Launch. Inputs (metadata order): x, codewords, indices, rotations, scales, bias.
// ---------------------------------------------------------------------------
extern "C" void kernel_launch(void* const* d_in, const int* in_sizes, int n_in,
                              void* d_out, int out_size)
{
    const float* x         = (const float*)d_in[0];
    const float* codewords = (const float*)d_in[1];
    const int*   indices   = (const int*)  d_in[2];   // int32 or int64 (detected on device)
    const float* rotations = (const float*)d_in[3];
    const float* scales    = (const float*)d_in[4];
    const float* bias      = (const float*)d_in[5];
    float*       out       = (float*)d_out;

    const int M = in_sizes[0] / EMBED;   // 8192 tokens

    dim3 block(NTHREADS);

    // Stage 1: decode weight into g_W
    dim3 grid1(EMBED / BN, RPT / BM, NTILES);     // (32, 8, 4)
    decode_kernel<<<grid1, block>>>(codewords, indices, rotations, scales);

    // Stage 2: y = x @ W^T + bias
    dim3 grid2(OUTF / BN, M / BM);                // (32, 64)
    linear_kernel<<<grid2, block>>>(x, bias, out);
}

// round 3
// speedup vs baseline: 2.5424x; 2.5424x over previous
#include <cuda_runtime.h>
#include <cuda_bf16.h>
#include <cstdint>
#include <cstddef>

// ---------------- problem constants ----------------
#define EMBED   4096
#define RPT     1024
#define NTILES  4
#define OUTF    4096

// ---------------- tiling ----------------
#define BM 128
#define BN 128
#define BK 32                    // k elems per chunk
#define NCHUNK (EMBED / BK)      // 128
#define NTHREADS 256

// smem tile geometry: 128 rows x 32 bf16 (64B) padded to 80B stride
#define ROWB 80
#define T_A_H 0
#define T_A_L 10240
#define T_B_H 20480
#define T_B_L 30720
#define STAGE 40960

// decoded weight, pre-split bf16 (32MB each)
__device__ __nv_bfloat16 g_Wh[(size_t)OUTF * EMBED];
__device__ __nv_bfloat16 g_Wl[(size_t)OUTF * EMBED];

// ---------------- helpers ----------------
__device__ __forceinline__ uint32_t smem_u32(const void* p) {
    uint32_t a;
    asm("{ .reg .u64 t; cvta.to.shared.u64 t, %1; cvt.u32.u64 %0, t; }" : "=r"(a) : "l"(p));
    return a;
}
__device__ __forceinline__ void ldsm4(uint32_t& r0, uint32_t& r1, uint32_t& r2, uint32_t& r3,
                                      uint32_t addr) {
    asm volatile("ldmatrix.sync.aligned.m8n8.x4.shared.b16 {%0,%1,%2,%3}, [%4];"
                 : "=r"(r0), "=r"(r1), "=r"(r2), "=r"(r3) : "r"(addr));
}
__device__ __forceinline__ void mma16816(float* c, const uint32_t* a, const uint32_t* b) {
    asm volatile(
        "mma.sync.aligned.m16n8k16.row.col.f32.bf16.bf16.f32 "
        "{%0,%1,%2,%3}, {%4,%5,%6,%7}, {%8,%9}, {%0,%1,%2,%3};"
        : "+f"(c[0]), "+f"(c[1]), "+f"(c[2]), "+f"(c[3])
        : "r"(a[0]), "r"(a[1]), "r"(a[2]), "r"(a[3]), "r"(b[0]), "r"(b[1]));
}
__device__ __forceinline__ void cpasync16(uint32_t dst, const void* src) {
    uint64_t g;
    asm("cvta.to.global.u64 %0, %1;" : "=l"(g) : "l"(src));
    asm volatile("cp.async.cg.shared.global [%0], [%1], 16;" :: "r"(dst), "l"(g));
}
#define CP_COMMIT() asm volatile("cp.async.commit_group;" ::: "memory")
#define CP_WAIT0()  asm volatile("cp.async.wait_group 0;" ::: "memory")

__device__ __forceinline__ uint32_t pack2(__nv_bfloat16 a, __nv_bfloat16 b) {
    return (uint32_t)__bfloat16_as_ushort(a) | ((uint32_t)__bfloat16_as_ushort(b) << 16);
}
__device__ __forceinline__ void split1(float v, __nv_bfloat16& h, __nv_bfloat16& l) {
    h = __float2bfloat16(v);
    l = __float2bfloat16(v - __bfloat162float(h));
}
__device__ __forceinline__ bool indices_are_i64(const int* __restrict__ p) {
    bool is64 = true;
#pragma unroll
    for (int i = 0; i < 8; ++i) is64 = is64 && (p[2 * i + 1] == 0);
    return is64;
}

// pack 16 fp32 -> hi/lo bf16x8 (two uint4 each)
__device__ __forceinline__ void split16(const float4* v, uint4* h, uint4* l) {
#pragma unroll
    for (int j = 0; j < 4; ++j) {
        __nv_bfloat16 h0, h1, h2, h3, l0, l1, l2, l3;
        split1(v[j].x, h0, l0); split1(v[j].y, h1, l1);
        split1(v[j].z, h2, l2); split1(v[j].w, h3, l3);
        ((uint32_t*)h)[2 * j]     = pack2(h0, h1);
        ((uint32_t*)h)[2 * j + 1] = pack2(h2, h3);
        ((uint32_t*)l)[2 * j]     = pack2(l0, l1);
        ((uint32_t*)l)[2 * j + 1] = pack2(l2, l3);
    }
}

// ---- per-warp mma over one staged chunk (BK=32) ----
// warp tile 64x32: wm=wid&1 (rows), wn=wid>>1 (cols); acc[mf][nf][4]
__device__ __forceinline__ void mma_chunk(uint32_t st, int wm, int wn, int lane,
                                          float acc[4][4][4]) {
#pragma unroll
    for (int ks = 0; ks < 2; ++ks) {
        const int kb = ks * 32;
        uint32_t bh[8], bl[8];
#pragma unroll
        for (int np = 0; np < 2; ++np) {
            int rB = wn * 32 + np * 16 + (lane & 7) + ((lane >> 4) & 1) * 8;
            int kc = kb + ((lane >> 3) & 1) * 16;
            uint32_t off = (uint32_t)(rB * ROWB + kc);
            ldsm4(bh[np * 4 + 0], bh[np * 4 + 1], bh[np * 4 + 2], bh[np * 4 + 3], st + T_B_H + off);
            ldsm4(bl[np * 4 + 0], bl[np * 4 + 1], bl[np * 4 + 2], bl[np * 4 + 3], st + T_B_L + off);
        }
#pragma unroll
        for (int mf = 0; mf < 4; ++mf) {
            int rA = wm * 64 + mf * 16 + (lane & 15);
            int ka = kb + (lane >> 4) * 16;
            uint32_t off = (uint32_t)(rA * ROWB + ka);
            uint32_t ah[4], al[4];
            ldsm4(ah[0], ah[1], ah[2], ah[3], st + T_A_H + off);
            ldsm4(al[0], al[1], al[2], al[3], st + T_A_L + off);
#pragma unroll
            for (int nf = 0; nf < 4; ++nf) {
                const uint32_t* bhp = &bh[(nf >> 1) * 4 + (nf & 1) * 2];
                const uint32_t* blp = &bl[(nf >> 1) * 4 + (nf & 1) * 2];
                mma16816(acc[mf][nf], ah, bhp);
                mma16816(acc[mf][nf], ah, blp);
                mma16816(acc[mf][nf], al, bhp);
            }
        }
    }
}

// ---------------------------------------------------------------------------
// Kernel 1: decode weight -> g_Wh/g_Wl  (single-stage, 2-sync pipeline)
// ---------------------------------------------------------------------------
__global__ __launch_bounds__(NTHREADS, 2)
void decode_kernel(const float* __restrict__ codewords,
                   const int*   __restrict__ idx_raw,
                   const float* __restrict__ rot,
                   const float* __restrict__ scales)
{
    extern __shared__ __align__(1024) char smem[];
    const uint32_t sb = smem_u32(smem);

    const int tid  = threadIdx.x;
    const int wid  = tid >> 5;
    const int lane = tid & 31;
    const int wm   = wid & 1;
    const int wn   = wid >> 1;
    const int t  = blockIdx.z;
    const int bm = blockIdx.y * BM;
    const int bn = blockIdx.x * BN;

    const bool is64 = indices_are_i64(idx_raw);

    // A loader: 2 threads per row, 16 fp32 each
    const int arow = tid >> 1;
    const int ahalf = tid & 1;
    const int grow = t * RPT + bm + arow;
    const int cidx = is64 ? idx_raw[2 * grow] : idx_raw[grow];
    const float* __restrict__ crow = codewords + (size_t)cidx * EMBED + ahalf * 16;

    const float* __restrict__ Rb = rot + (size_t)t * EMBED * EMBED + bn;

    float acc[4][4][4];
#pragma unroll
    for (int i = 0; i < 4; ++i)
#pragma unroll
        for (int j = 0; j < 4; ++j)
#pragma unroll
            for (int q = 0; q < 4; ++q) acc[i][j][q] = 0.0f;

#pragma unroll 1
    for (int c = 0; c < NCHUNK; ++c) {
        const int k0 = c * BK;
        // load A (gathered codeword rows)
        float4 av[4];
#pragma unroll
        for (int j = 0; j < 4; ++j)
            av[j] = *reinterpret_cast<const float4*>(crow + k0 + j * 4);
        // load B: R rows (coalesced along e), to be transposed into [e][d]
        float bv0[2][4], bv1[2][4];
#pragma unroll
        for (int pp = 0; pp < 2; ++pp) {
            int p = wid + 8 * pp;          // d-pair index 0..15
            int dd = 2 * p;
#pragma unroll
            for (int j = 0; j < 4; ++j) {
                int e = lane + 32 * j;
                bv0[pp][j] = Rb[(size_t)(k0 + dd)     * EMBED + e];
                bv1[pp][j] = Rb[(size_t)(k0 + dd + 1) * EMBED + e];
            }
        }
        __syncthreads();   // previous chunk's readers done
        // store A
        {
            uint4 h[2], l[2];
            split16(av, h, l);
            uint32_t base = sb + (uint32_t)(arow * ROWB + ahalf * 32);
            *reinterpret_cast<uint4*>((char*)smem + (base - sb) + T_A_H)      = h[0];
            *reinterpret_cast<uint4*>((char*)smem + (base - sb) + T_A_H + 16) = h[1];
            *reinterpret_cast<uint4*>((char*)smem + (base - sb) + T_A_L)      = l[0];
            *reinterpret_cast<uint4*>((char*)smem + (base - sb) + T_A_L + 16) = l[1];
        }
        // store B transposed + split
#pragma unroll
        for (int pp = 0; pp < 2; ++pp) {
            int p = wid + 8 * pp;
#pragma unroll
            for (int j = 0; j < 4; ++j) {
                int e = lane + 32 * j;
                __nv_bfloat16 h0, h1, l0, l1;
                split1(bv0[pp][j], h0, l0);
                split1(bv1[pp][j], h1, l1);
                uint32_t off = (uint32_t)(e * ROWB + p * 4);
                *reinterpret_cast<uint32_t*>(smem + T_B_H + off) = pack2(h0, h1);
                *reinterpret_cast<uint32_t*>(smem + T_B_L + off) = pack2(l0, l1);
            }
        }
        __syncthreads();
        mma_chunk(sb, wm, wn, lane, acc);
    }

    // epilogue: scale, split, store to g_Wh/g_Wl
    const float s = scales[t];
#pragma unroll
    for (int mf = 0; mf < 4; ++mf) {
#pragma unroll
        for (int nf = 0; nf < 4; ++nf) {
            int row = t * RPT + bm + wm * 64 + mf * 16 + (lane >> 2);
            int col = bn + wn * 32 + nf * 8 + (lane & 3) * 2;
            float v0 = acc[mf][nf][0] * s, v1 = acc[mf][nf][1] * s;
            float v2 = acc[mf][nf][2] * s, v3 = acc[mf][nf][3] * s;
            __nv_bfloat16 h0, h1, h2, h3, l0, l1, l2, l3;
            split1(v0, h0, l0); split1(v1, h1, l1);
            split1(v2, h2, l2); split1(v3, h3, l3);
            size_t g0 = (size_t)row * EMBED + col;
            size_t g1 = (size_t)(row + 8) * EMBED + col;
            *reinterpret_cast<uint32_t*>(g_Wh + g0) = pack2(h0, h1);
            *reinterpret_cast<uint32_t*>(g_Wl + g0) = pack2(l0, l1);
            *reinterpret_cast<uint32_t*>(g_Wh + g1) = pack2(h2, h3);
            *reinterpret_cast<uint32_t*>(g_Wl + g1) = pack2(l2, l3);
        }
    }
}

// ---------------------------------------------------------------------------
// Kernel 2: out = x @ W^T + bias  (double-buffered, cp.async for W tiles)
// ---------------------------------------------------------------------------
__global__ __launch_bounds__(NTHREADS, 2)
void linear_kernel(const float* __restrict__ x,
                   const float* __restrict__ bias,
                   float*       __restrict__ out)
{
    extern __shared__ __align__(1024) char smem[];
    const uint32_t sb = smem_u32(smem);

    const int tid  = threadIdx.x;
    const int wid  = tid >> 5;
    const int lane = tid & 31;
    const int wm   = wid & 1;
    const int wn   = wid >> 1;
    const int bm = blockIdx.y * BM;
    const int bn = blockIdx.x * BN;

    const int arow = tid >> 1;
    const int ahalf = tid & 1;
    const float* __restrict__ xrow = x + (size_t)(bm + arow) * EMBED + ahalf * 16;

    // B cp.async mapping: 2 ops x (hi+lo) per thread
    const int brow0 = tid >> 2;          // f = tid
    const int bq0   = tid & 3;
    const int brow1 = (tid + 256) >> 2;  // f = tid + 256
    const int bq1   = tid & 3;

    float acc[4][4][4];
#pragma unroll
    for (int i = 0; i < 4; ++i)
#pragma unroll
        for (int j = 0; j < 4; ++j)
#pragma unroll
            for (int q = 0; q < 4; ++q) acc[i][j][q] = 0.0f;

    auto issueB = [&](int c, uint32_t st) {
        const int k0 = c * BK;
        cpasync16(st + T_B_H + (uint32_t)(brow0 * ROWB + bq0 * 16),
                  g_Wh + (size_t)(bn + brow0) * EMBED + k0 + bq0 * 8);
        cpasync16(st + T_B_L + (uint32_t)(brow0 * ROWB + bq0 * 16),
                  g_Wl + (size_t)(bn + brow0) * EMBED + k0 + bq0 * 8);
        cpasync16(st + T_B_H + (uint32_t)(brow1 * ROWB + bq1 * 16),
                  g_Wh + (size_t)(bn + brow1) * EMBED + k0 + bq1 * 8);
        cpasync16(st + T_B_L + (uint32_t)(brow1 * ROWB + bq1 * 16),
                  g_Wl + (size_t)(bn + brow1) * EMBED + k0 + bq1 * 8);
    };
    auto storeA = [&](uint32_t st, const float4* av) {
        uint4 h[2], l[2];
        split16(av, h, l);
        uint32_t off = (uint32_t)(arow * ROWB + ahalf * 32);
        char* p = (char*)smem;
        *reinterpret_cast<uint4*>(p + T_A_H + off)      = h[0];
        *reinterpret_cast<uint4*>(p + T_A_H + off + 16) = h[1];
        *reinterpret_cast<uint4*>(p + T_A_L + off)      = l[0];
        *reinterpret_cast<uint4*>(p + T_A_L + off + 16) = l[1];
        (void)st;
    };
    auto storeA_st = [&](int stage, const float4* av) {
        uint4 h[2], l[2];
        split16(av, h, l);
        uint32_t off = (uint32_t)(stage * STAGE + arow * ROWB + ahalf * 32);
        char* p = (char*)smem;
        *reinterpret_cast<uint4*>(p + T_A_H + off)      = h[0];
        *reinterpret_cast<uint4*>(p + T_A_H + off + 16) = h[1];
        *reinterpret_cast<uint4*>(p + T_A_L + off)      = l[0];
        *reinterpret_cast<uint4*>(p + T_A_L + off + 16) = l[1];
    };
    (void)storeA;

    // prologue: chunk 0 -> stage 0
    {
        float4 av[4];
#pragma unroll
        for (int j = 0; j < 4; ++j)
            av[j] = *reinterpret_cast<const float4*>(xrow + 0 + j * 4);
        issueB(0, sb);
        CP_COMMIT();
        storeA_st(0, av);
        CP_WAIT0();
        __syncthreads();
    }

#pragma unroll 1
    for (int c = 0; c < NCHUNK; ++c) {
        const int s = c & 1;
        const uint32_t st = sb + (uint32_t)s * STAGE;
        const bool more = (c + 1 < NCHUNK);
        float4 av[4];
        if (more) {
            const int k1 = (c + 1) * BK;
#pragma unroll
            for (int j = 0; j < 4; ++j)
                av[j] = *reinterpret_cast<const float4*>(xrow + k1 + j * 4);
            issueB(c + 1, sb + (uint32_t)(s ^ 1) * STAGE);
            CP_COMMIT();
        }
        mma_chunk(st, wm, wn, lane, acc);
        if (more) {
            storeA_st(s ^ 1, av);
            CP_WAIT0();
        }
        __syncthreads();
    }

    // epilogue
#pragma unroll
    for (int nf = 0; nf < 4; ++nf) {
        int col = bn + wn * 32 + nf * 8 + (lane & 3) * 2;
        float b0 = bias[col], b1 = bias[col + 1];
#pragma unroll
        for (int mf = 0; mf < 4; ++mf) {
            int row = bm + wm * 64 + mf * 16 + (lane >> 2);
            float2 v0 = make_float2(acc[mf][nf][0] + b0, acc[mf][nf][1] + b1);
            float2 v1 = make_float2(acc[mf][nf][2] + b0, acc[mf][nf][3] + b1);
            *reinterpret_cast<float2*>(out + (size_t)row * OUTF + col)       = v0;
            *reinterpret_cast<float2*>(out + (size_t)(row + 8) * OUTF + col) = v1;
        }
    }
}

// ---------------------------------------------------------------------------
// Launch. Inputs: x, codewords, indices, rotations, scales, bias.
// ---------------------------------------------------------------------------
extern "C" void kernel_launch(void* const* d_in, const int* in_sizes, int n_in,
                              void* d_out, int out_size)
{
    const float* x         = (const float*)d_in[0];
    const float* codewords = (const float*)d_in[1];
    const int*   indices   = (const int*)  d_in[2];
    const float* rotations = (const float*)d_in[3];
    const float* scales    = (const float*)d_in[4];
    const float* bias      = (const float*)d_in[5];
    float*       out       = (float*)d_out;

    const int M = in_sizes[0] / EMBED;   // 8192

    static bool attr_set = false;
    if (!attr_set) {
        cudaFuncSetAttribute(decode_kernel, cudaFuncAttributeMaxDynamicSharedMemorySize, STAGE);
        cudaFuncSetAttribute(linear_kernel, cudaFuncAttributeMaxDynamicSharedMemorySize, 2 * STAGE);
        attr_set = true;
    }

    dim3 block(NTHREADS);
    dim3 grid1(EMBED / BN, RPT / BM, NTILES);   // (32, 8, 4)
    decode_kernel<<<grid1, block, STAGE>>>(codewords, indices, rotations, scales);

    dim3 grid2(OUTF / BN, M / BM);              // (32, 64)
    linear_kernel<<<grid2, block, 2 * STAGE>>>(x, bias, out);
}

// round 4
// speedup vs baseline: 3.0404x; 1.1959x over previous
#include <cuda_runtime.h>
#include <cuda_bf16.h>
#include <cstdint>
#include <cstddef>

// ---------------- problem constants ----------------
#define EMBED   4096
#define RPT     1024
#define NTILES  4
#define OUTF    4096
#define MTOK    8192            // B*S tokens

// ---------------- GEMM tiling ----------------
#define BM 128
#define BN 256
#define BK 64                   // 64 bf16 = 128B rows -> SW128 swizzle
#define NCHUNK (EMBED / BK)     // 64
#define NT 256                  // threads

// smem stage layout (bytes, relative to 1KB-aligned base)
#define OFF_AH 0
#define OFF_AL 16384
#define OFF_BH 32768
#define OFF_BL 65536
#define STAGE_BYTES 98304       // 96KB
#define SMEM_DYN (2 * STAGE_BYTES + 1024)

// ---------------- device scratch (pre-split bf16) ----------------
__device__ __nv_bfloat16 g_Xh[(size_t)MTOK * EMBED];            // 64MB
__device__ __nv_bfloat16 g_Xl[(size_t)MTOK * EMBED];
__device__ __nv_bfloat16 g_Ah[(size_t)OUTF * EMBED];            // 32MB (gathered codewords)
__device__ __nv_bfloat16 g_Al[(size_t)OUTF * EMBED];
__device__ __nv_bfloat16 g_Rth[(size_t)NTILES * EMBED * EMBED]; // 128MB (R^T, K-major)
__device__ __nv_bfloat16 g_Rtl[(size_t)NTILES * EMBED * EMBED];
__device__ __nv_bfloat16 g_Wh[(size_t)OUTF * EMBED];            // 32MB (decoded W)
__device__ __nv_bfloat16 g_Wl[(size_t)OUTF * EMBED];

// ---------------- helpers ----------------
__device__ __forceinline__ uint32_t smem_u32(const void* p) {
    uint32_t a;
    asm("{ .reg .u64 t; cvta.to.shared.u64 t, %1; cvt.u32.u64 %0, t; }" : "=r"(a) : "l"(p));
    return a;
}
__device__ __forceinline__ uint32_t swz(uint32_t b) { return b ^ ((b >> 3) & 0x70); }

__device__ __forceinline__ void ldsm4(uint32_t& r0, uint32_t& r1, uint32_t& r2, uint32_t& r3,
                                      uint32_t addr) {
    asm volatile("ldmatrix.sync.aligned.m8n8.x4.shared.b16 {%0,%1,%2,%3}, [%4];"
                 : "=r"(r0), "=r"(r1), "=r"(r2), "=r"(r3) : "r"(addr));
}
__device__ __forceinline__ void mma16816(float* c, const uint32_t* a, const uint32_t* b) {
    asm volatile(
        "mma.sync.aligned.m16n8k16.row.col.f32.bf16.bf16.f32 "
        "{%0,%1,%2,%3}, {%4,%5,%6,%7}, {%8,%9}, {%0,%1,%2,%3};"
        : "+f"(c[0]), "+f"(c[1]), "+f"(c[2]), "+f"(c[3])
        : "r"(a[0]), "r"(a[1]), "r"(a[2]), "r"(a[3]), "r"(b[0]), "r"(b[1]));
}
__device__ __forceinline__ void cpasync16(uint32_t dst, const void* src) {
    uint64_t g;
    asm("cvta.to.global.u64 %0, %1;" : "=l"(g) : "l"(src));
    asm volatile("cp.async.cg.shared.global [%0], [%1], 16;" :: "r"(dst), "l"(g));
}
#define CP_COMMIT() asm volatile("cp.async.commit_group;" ::: "memory")
#define CP_WAIT0()  asm volatile("cp.async.wait_group 0;" ::: "memory")

__device__ __forceinline__ uint32_t pack2(__nv_bfloat16 a, __nv_bfloat16 b) {
    return (uint32_t)__bfloat16_as_ushort(a) | ((uint32_t)__bfloat16_as_ushort(b) << 16);
}
__device__ __forceinline__ void split1(float v, __nv_bfloat16& h, __nv_bfloat16& l) {
    h = __float2bfloat16(v);
    l = __float2bfloat16(v - __bfloat162float(h));
}
__device__ __forceinline__ void split4(float4 v, uint2& h, uint2& l) {
    __nv_bfloat16 h0, h1, h2, h3, l0, l1, l2, l3;
    split1(v.x, h0, l0); split1(v.y, h1, l1);
    split1(v.z, h2, l2); split1(v.w, h3, l3);
    h = make_uint2(pack2(h0, h1), pack2(h2, h3));
    l = make_uint2(pack2(l0, l1), pack2(l2, l3));
}
__device__ __forceinline__ bool indices_are_i64(const int* __restrict__ p) {
    bool is64 = true;
#pragma unroll
    for (int i = 0; i < 8; ++i) is64 = is64 && (p[2 * i + 1] == 0);
    return is64;
}

// ---------------------------------------------------------------------------
// Prep 1: split x -> g_Xh/g_Xl
// ---------------------------------------------------------------------------
__global__ __launch_bounds__(NT)
void split_x_kernel(const float* __restrict__ x)
{
#pragma unroll
    for (int j = 0; j < 4; ++j) {
        size_t f4 = (size_t)blockIdx.x * 1024 + threadIdx.x + j * 256;
        float4 v = *reinterpret_cast<const float4*>(x + f4 * 4);
        uint2 h, l;
        split4(v, h, l);
        *reinterpret_cast<uint2*>(g_Xh + f4 * 4) = h;
        *reinterpret_cast<uint2*>(g_Xl + f4 * 4) = l;
    }
}

// ---------------------------------------------------------------------------
// Prep 2: gather + split codewords -> g_Ah/g_Al  (one block per output row)
// ---------------------------------------------------------------------------
__global__ __launch_bounds__(NT)
void gather_split_kernel(const float* __restrict__ codewords,
                         const int*   __restrict__ idx_raw)
{
    const int b = blockIdx.x;                 // 0..4095 = t*1024 + r
    const bool is64 = indices_are_i64(idx_raw);
    const int cidx = is64 ? idx_raw[2 * b] : idx_raw[b];
    const float* __restrict__ src = codewords + (size_t)cidx * EMBED;
#pragma unroll
    for (int j = 0; j < 4; ++j) {
        int e4 = threadIdx.x + j * 256;       // 0..1023
        float4 v = *reinterpret_cast<const float4*>(src + e4 * 4);
        uint2 h, l;
        split4(v, h, l);
        size_t o = (size_t)b * EMBED + e4 * 4;
        *reinterpret_cast<uint2*>(g_Ah + o) = h;
        *reinterpret_cast<uint2*>(g_Al + o) = l;
    }
}

// ---------------------------------------------------------------------------
// Prep 3: transpose + split rotations: R[t][d][e] -> g_Rth/g_Rtl [t][e][d]
// block tile: 32 d x 128 e
// ---------------------------------------------------------------------------
__global__ __launch_bounds__(NT)
void transpose_split_kernel(const float* __restrict__ rot)
{
    __shared__ float sm[32][132];
    const int xb = blockIdx.x;   // e block (128 wide)
    const int yb = blockIdx.y;   // d block (32 wide)
    const int t  = blockIdx.z;
    const int tid = threadIdx.x;

    // read 32 d-rows x 128 e, coalesced
#pragma unroll
    for (int p = 0; p < 4; ++p) {
        int dd = p * 8 + (tid >> 5);
        int e4 = (tid & 31);
        float4 v = *reinterpret_cast<const float4*>(
            rot + ((size_t)t * EMBED + yb * 32 + dd) * EMBED + xb * 128 + e4 * 4);
        *reinterpret_cast<float4*>(&sm[dd][e4 * 4]) = v;
    }
    __syncthreads();

    // write: rows e (128), cols d (32) as bf16 pairs (d-contiguous)
#pragma unroll
    for (int p = 0; p < 8; ++p) {
        int e  = p * 16 + (tid >> 4);
        int dp = tid & 15;
        float v0 = sm[2 * dp][e];
        float v1 = sm[2 * dp + 1][e];
        __nv_bfloat16 h0, h1, l0, l1;
        split1(v0, h0, l0); split1(v1, h1, l1);
        size_t o = (size_t)t * EMBED * EMBED + (size_t)(xb * 128 + e) * EMBED + yb * 32 + 2 * dp;
        *reinterpret_cast<uint32_t*>(g_Rth + o) = pack2(h0, h1);
        *reinterpret_cast<uint32_t*>(g_Rtl + o) = pack2(l0, l1);
    }
}

// ---------------------------------------------------------------------------
// Unified GEMM: C[m][n] = sum_k A[m][k]*B[n][k]  (A,B pre-split bf16, 3 terms)
// CTA 128x256, 8 warps (2M x 4N), warp tile 64x64, BK=64, SW128, double buffer.
// MODE 0: out = C + bias (fp32)          [linear]
// MODE 1: g_W = split(C * scales[t])     [decode]
// ---------------------------------------------------------------------------
template<int MODE>
__global__ __launch_bounds__(NT, 1)
void gemm_kernel(const __nv_bfloat16* __restrict__ Ah, const __nv_bfloat16* __restrict__ Al,
                 const __nv_bfloat16* __restrict__ Bh, const __nv_bfloat16* __restrict__ Bl,
                 const float* __restrict__ bias, float* __restrict__ out,
                 const float* __restrict__ scales)
{
    extern __shared__ char smraw[];
    const uint32_t sraw = smem_u32(smraw);
    const uint32_t sb   = (sraw + 1023u) & ~1023u;

    const int tid  = threadIdx.x;
    const int wid  = tid >> 5;
    const int lane = tid & 31;
    const int wm   = wid & 1;        // 0..1
    const int wn   = wid >> 1;       // 0..3
    const int bm   = blockIdx.y * BM;
    const int bn   = blockIdx.x * BN;

    if (MODE == 1) {
        // decode: B = R^T of tile t
        const int t = bm >> 10;
        Bh += (size_t)t * EMBED * EMBED;
        Bl += (size_t)t * EMBED * EMBED;
    }

    // cp.async per-thread coords: k16 = tid&7 (16B col), rbase = tid>>3
    const int k16   = tid & 7;
    const int rbase = tid >> 3;      // 0..31

    float acc[4][8][4];
#pragma unroll
    for (int i = 0; i < 4; ++i)
#pragma unroll
        for (int j = 0; j < 8; ++j)
#pragma unroll
            for (int q = 0; q < 4; ++q) acc[i][j][q] = 0.0f;

    auto issue = [&](int c, int stage) {
        const uint32_t st = sb + (uint32_t)stage * STAGE_BYTES;
        const size_t kofs = (size_t)c * BK + k16 * 8;
#pragma unroll
        for (int i = 0; i < 4; ++i) {
            const int row = rbase + i * 32;                 // 0..127
            const uint32_t d = swz((uint32_t)(row * 128 + k16 * 16));
            cpasync16(st + OFF_AH + d, Ah + (size_t)(bm + row) * EMBED + kofs);
            cpasync16(st + OFF_AL + d, Al + (size_t)(bm + row) * EMBED + kofs);
        }
#pragma unroll
        for (int i = 0; i < 8; ++i) {
            const int row = rbase + i * 32;                 // 0..255
            const uint32_t d = swz((uint32_t)(row * 128 + k16 * 16));
            cpasync16(st + OFF_BH + d, Bh + (size_t)(bn + row) * EMBED + kofs);
            cpasync16(st + OFF_BL + d, Bl + (size_t)(bn + row) * EMBED + kofs);
        }
    };

    issue(0, 0);
    CP_COMMIT();
    CP_WAIT0();
    __syncthreads();

#pragma unroll 1
    for (int c = 0; c < NCHUNK; ++c) {
        const uint32_t st = sb + (uint32_t)(c & 1) * STAGE_BYTES;
        const bool more = (c + 1 < NCHUNK);
        if (more) {
            issue(c + 1, (c + 1) & 1);
            CP_COMMIT();
        }
#pragma unroll
        for (int ks = 0; ks < 4; ++ks) {
            // B fragments: 64 n per warp
            uint32_t bh[16], bl[16];
#pragma unroll
            for (int np = 0; np < 4; ++np) {
                const int rB = wn * 64 + np * 16 + (lane & 7) + ((lane >> 4) & 1) * 8;
                const uint32_t off = swz((uint32_t)(rB * 128 + ks * 32 + ((lane >> 3) & 1) * 16));
                ldsm4(bh[np * 4 + 0], bh[np * 4 + 1], bh[np * 4 + 2], bh[np * 4 + 3],
                      st + OFF_BH + off);
                ldsm4(bl[np * 4 + 0], bl[np * 4 + 1], bl[np * 4 + 2], bl[np * 4 + 3],
                      st + OFF_BL + off);
            }
#pragma unroll
            for (int mf = 0; mf < 4; ++mf) {
                const int rA = wm * 64 + mf * 16 + (lane & 15);
                const uint32_t off = swz((uint32_t)(rA * 128 + ks * 32 + (lane >> 4) * 16));
                uint32_t ah[4], al[4];
                ldsm4(ah[0], ah[1], ah[2], ah[3], st + OFF_AH + off);
                ldsm4(al[0], al[1], al[2], al[3], st + OFF_AL + off);
#pragma unroll
                for (int nf = 0; nf < 8; ++nf) {
                    const uint32_t* bhp = &bh[(nf >> 1) * 4 + (nf & 1) * 2];
                    const uint32_t* blp = &bl[(nf >> 1) * 4 + (nf & 1) * 2];
                    mma16816(acc[mf][nf], ah, bhp);
                    mma16816(acc[mf][nf], ah, blp);
                    mma16816(acc[mf][nf], al, bhp);
                }
            }
        }
        if (more) CP_WAIT0();
        __syncthreads();
    }

    // ---- epilogue ----
    if (MODE == 0) {
#pragma unroll
        for (int nf = 0; nf < 8; ++nf) {
            const int col = bn + wn * 64 + nf * 8 + (lane & 3) * 2;
            const float b0 = bias[col], b1 = bias[col + 1];
#pragma unroll
            for (int mf = 0; mf < 4; ++mf) {
                const int row = bm + wm * 64 + mf * 16 + (lane >> 2);
                float2 v0 = make_float2(acc[mf][nf][0] + b0, acc[mf][nf][1] + b1);
                float2 v1 = make_float2(acc[mf][nf][2] + b0, acc[mf][nf][3] + b1);
                *reinterpret_cast<float2*>(out + (size_t)row * OUTF + col)       = v0;
                *reinterpret_cast<float2*>(out + (size_t)(row + 8) * OUTF + col) = v1;
            }
        }
    } else {
        const float s = scales[bm >> 10];
#pragma unroll
        for (int nf = 0; nf < 8; ++nf) {
            const int col = bn + wn * 64 + nf * 8 + (lane & 3) * 2;
#pragma unroll
            for (int mf = 0; mf < 4; ++mf) {
                const int row = bm + wm * 64 + mf * 16 + (lane >> 2);
                float v0 = acc[mf][nf][0] * s, v1 = acc[mf][nf][1] * s;
                float v2 = acc[mf][nf][2] * s, v3 = acc[mf][nf][3] * s;
                __nv_bfloat16 h0, h1, h2, h3, l0, l1, l2, l3;
                split1(v0, h0, l0); split1(v1, h1, l1);
                split1(v2, h2, l2); split1(v3, h3, l3);
                size_t g0 = (size_t)row * EMBED + col;
                size_t g1 = (size_t)(row + 8) * EMBED + col;
                *reinterpret_cast<uint32_t*>(g_Wh + g0) = pack2(h0, h1);
                *reinterpret_cast<uint32_t*>(g_Wl + g0) = pack2(l0, l1);
                *reinterpret_cast<uint32_t*>(g_Wh + g1) = pack2(h2, h3);
                *reinterpret_cast<uint32_t*>(g_Wl + g1) = pack2(l2, l3);
            }
        }
    }
}

// ---------------------------------------------------------------------------
// Launch. Inputs: x, codewords, indices, rotations, scales, bias.
// ---------------------------------------------------------------------------
extern "C" void kernel_launch(void* const* d_in, const int* in_sizes, int n_in,
                              void* d_out, int out_size)
{
    const float* x         = (const float*)d_in[0];
    const float* codewords = (const float*)d_in[1];
    const int*   indices   = (const int*)  d_in[2];
    const float* rotations = (const float*)d_in[3];
    const float* scales    = (const float*)d_in[4];
    const float* bias      = (const float*)d_in[5];
    float*       out       = (float*)d_out;

    const int M = in_sizes[0] / EMBED;   // 8192

    cudaFuncSetAttribute(gemm_kernel<0>, cudaFuncAttributeMaxDynamicSharedMemorySize, SMEM_DYN);
    cudaFuncSetAttribute(gemm_kernel<1>, cudaFuncAttributeMaxDynamicSharedMemorySize, SMEM_DYN);

    void *pXh, *pXl, *pAh, *pAl, *pRh, *pRl, *pWh, *pWl;
    cudaGetSymbolAddress(&pXh, g_Xh); cudaGetSymbolAddress(&pXl, g_Xl);
    cudaGetSymbolAddress(&pAh, g_Ah); cudaGetSymbolAddress(&pAl, g_Al);
    cudaGetSymbolAddress(&pRh, g_Rth); cudaGetSymbolAddress(&pRl, g_Rtl);
    cudaGetSymbolAddress(&pWh, g_Wh); cudaGetSymbolAddress(&pWl, g_Wl);

    // prep
    split_x_kernel<<<(size_t)M * EMBED / 4096, NT>>>(x);
    gather_split_kernel<<<NTILES * RPT, NT>>>(codewords, indices);
    transpose_split_kernel<<<dim3(EMBED / 128, EMBED / 32, NTILES), NT>>>(rotations);

    // decode: W[4096 x 4096]
    gemm_kernel<1><<<dim3(EMBED / BN, (NTILES * RPT) / BM), NT, SMEM_DYN>>>(
        (const __nv_bfloat16*)pAh, (const __nv_bfloat16*)pAl,
        (const __nv_bfloat16*)pRh, (const __nv_bfloat16*)pRl,
        nullptr, nullptr, scales);

    // linear: out[8192 x 4096]
    gemm_kernel<0><<<dim3(OUTF / BN, M / BM), NT, SMEM_DYN>>>(
        (const __nv_bfloat16*)pXh, (const __nv_bfloat16*)pXl,
        (const __nv_bfloat16*)pWh, (const __nv_bfloat16*)pWl,
        bias, out, nullptr);
}

// round 5
// speedup vs baseline: 4.3642x; 1.4354x over previous
#include <cuda_runtime.h>
#include <cuda_fp16.h>
#include <cstdint>
#include <cstddef>

// ---------------- problem constants ----------------
#define EMBED   4096
#define RPT     1024
#define NTILES  4
#define OUTF    4096
#define MTOK    8192            // B*S tokens

// ---------------- GEMM tiling ----------------
#define BM 128
#define BN 256
#define BK 64                   // 64 fp16 = 128B rows -> SW128 swizzle
#define NCHUNK (EMBED / BK)     // 64
#define NT 256

// ---------------- device scratch (fp16) ----------------
__device__ __half g_Xh[(size_t)MTOK * EMBED];             // x rounded fp16 (64MB)
__device__ __half g_Ah[(size_t)OUTF * EMBED];             // gathered cw*256 hi (32MB)
__device__ __half g_Al[(size_t)OUTF * EMBED];             // gathered cw*256 lo
__device__ __half g_Rh[(size_t)NTILES * EMBED * EMBED];   // R^T single fp16 (128MB)
__device__ __half g_Wh[(size_t)OUTF * EMBED];             // decoded W*256 hi
__device__ __half g_Wl[(size_t)OUTF * EMBED];             // decoded W*256 lo

// ---------------- helpers ----------------
__device__ __forceinline__ uint32_t smem_u32(const void* p) {
    uint32_t a;
    asm("{ .reg .u64 t; cvta.to.shared.u64 t, %1; cvt.u32.u64 %0, t; }" : "=r"(a) : "l"(p));
    return a;
}
__device__ __forceinline__ uint32_t swz(uint32_t b) { return b ^ ((b >> 3) & 0x70); }

__device__ __forceinline__ void ldsm4(uint32_t& r0, uint32_t& r1, uint32_t& r2, uint32_t& r3,
                                      uint32_t addr) {
    asm volatile("ldmatrix.sync.aligned.m8n8.x4.shared.b16 {%0,%1,%2,%3}, [%4];"
                 : "=r"(r0), "=r"(r1), "=r"(r2), "=r"(r3) : "r"(addr));
}
__device__ __forceinline__ void mma16816(float* c, const uint32_t* a, const uint32_t* b) {
    asm volatile(
        "mma.sync.aligned.m16n8k16.row.col.f32.f16.f16.f32 "
        "{%0,%1,%2,%3}, {%4,%5,%6,%7}, {%8,%9}, {%0,%1,%2,%3};"
        : "+f"(c[0]), "+f"(c[1]), "+f"(c[2]), "+f"(c[3])
        : "r"(a[0]), "r"(a[1]), "r"(a[2]), "r"(a[3]), "r"(b[0]), "r"(b[1]));
}
__device__ __forceinline__ void cpasync16(uint32_t dst, const void* src) {
    uint64_t g;
    asm("cvta.to.global.u64 %0, %1;" : "=l"(g) : "l"(src));
    asm volatile("cp.async.cg.shared.global [%0], [%1], 16;" :: "r"(dst), "l"(g));
}
#define CP_COMMIT() asm volatile("cp.async.commit_group;" ::: "memory")
#define CP_WAIT0()  asm volatile("cp.async.wait_group 0;" ::: "memory")

__device__ __forceinline__ uint32_t pack2(__half a, __half b) {
    return (uint32_t)__half_as_ushort(a) | ((uint32_t)__half_as_ushort(b) << 16);
}
__device__ __forceinline__ void split1(float v, __half& h, __half& l) {
    h = __float2half_rn(v);
    l = __float2half_rn(v - __half2float(h));
}
__device__ __forceinline__ bool indices_are_i64(const int* __restrict__ p) {
    bool is64 = true;
#pragma unroll
    for (int i = 0; i < 8; ++i) is64 = is64 && (p[2 * i + 1] == 0);
    return is64;
}

// ---------------------------------------------------------------------------
// Prep 1: x -> g_Xh (single fp16, the linear GEMM's rounded operand)
// ---------------------------------------------------------------------------
__global__ __launch_bounds__(NT)
void conv_x_kernel(const float* __restrict__ x)
{
#pragma unroll
    for (int j = 0; j < 4; ++j) {
        size_t f4 = (size_t)blockIdx.x * 1024 + threadIdx.x + j * 256;
        float4 v = *reinterpret_cast<const float4*>(x + f4 * 4);
        uint2 h;
        h.x = pack2(__float2half_rn(v.x), __float2half_rn(v.y));
        h.y = pack2(__float2half_rn(v.z), __float2half_rn(v.w));
        *reinterpret_cast<uint2*>(g_Xh + f4 * 4) = h;
    }
}

// ---------------------------------------------------------------------------
// Prep 2: gather + scale(256) + split codewords -> g_Ah/g_Al
// ---------------------------------------------------------------------------
__global__ __launch_bounds__(NT)
void gather_split_kernel(const float* __restrict__ codewords,
                         const int*   __restrict__ idx_raw)
{
    const int b = blockIdx.x;                 // 0..4095 = t*1024 + r
    const bool is64 = indices_are_i64(idx_raw);
    const int cidx = is64 ? idx_raw[2 * b] : idx_raw[b];
    const float* __restrict__ src = codewords + (size_t)cidx * EMBED;
#pragma unroll
    for (int j = 0; j < 4; ++j) {
        int e4 = threadIdx.x + j * 256;
        float4 v = *reinterpret_cast<const float4*>(src + e4 * 4);
        __half h0, h1, h2, h3, l0, l1, l2, l3;
        split1(v.x * 256.0f, h0, l0); split1(v.y * 256.0f, h1, l1);
        split1(v.z * 256.0f, h2, l2); split1(v.w * 256.0f, h3, l3);
        size_t o = (size_t)b * EMBED + e4 * 4;
        *reinterpret_cast<uint2*>(g_Ah + o) = make_uint2(pack2(h0, h1), pack2(h2, h3));
        *reinterpret_cast<uint2*>(g_Al + o) = make_uint2(pack2(l0, l1), pack2(l2, l3));
    }
}

// ---------------------------------------------------------------------------
// Prep 3: transpose rotations: R[t][d][e] -> g_Rh [t][e][d] single fp16
// block tile: 32 d x 128 e
// ---------------------------------------------------------------------------
__global__ __launch_bounds__(NT)
void transpose_kernel(const float* __restrict__ rot)
{
    __shared__ float sm[32][132];
    const int xb = blockIdx.x;   // e block (128)
    const int yb = blockIdx.y;   // d block (32)
    const int t  = blockIdx.z;
    const int tid = threadIdx.x;

#pragma unroll
    for (int p = 0; p < 4; ++p) {
        int dd = p * 8 + (tid >> 5);
        int e4 = (tid & 31);
        float4 v = *reinterpret_cast<const float4*>(
            rot + ((size_t)t * EMBED + yb * 32 + dd) * EMBED + xb * 128 + e4 * 4);
        *reinterpret_cast<float4*>(&sm[dd][e4 * 4]) = v;
    }
    __syncthreads();

#pragma unroll
    for (int p = 0; p < 8; ++p) {
        int e  = p * 16 + (tid >> 4);
        int dp = tid & 15;
        __half h0 = __float2half_rn(sm[2 * dp][e]);
        __half h1 = __float2half_rn(sm[2 * dp + 1][e]);
        size_t o = (size_t)t * EMBED * EMBED + (size_t)(xb * 128 + e) * EMBED + yb * 32 + 2 * dp;
        *reinterpret_cast<uint32_t*>(g_Rh + o) = pack2(h0, h1);
    }
}

// ---------------------------------------------------------------------------
// Unified 2-term GEMM: C = A @ B^T over fp16, fp32 accum.
// MODE 0 (linear): A = Xh (single),  B = Wh + Wl (split).  out = C/256 + bias
// MODE 1 (decode): A = Ah + Al (split), B = Rh (single).   g_W = split(C * scales[t])
// CTA 128x256, 8 warps 64x64, BK=64, SW128, double-buffered cp.async.
// ---------------------------------------------------------------------------
template<int MODE>
__global__ __launch_bounds__(NT, 1)
void gemm_kernel(const float* __restrict__ bias, float* __restrict__ out,
                 const float* __restrict__ scales)
{
    // smem stage offsets
    constexpr uint32_t OFF_A0 = 0;                                 // Ah
    constexpr uint32_t OFF_A1 = 16384;                             // Al (decode only)
    constexpr uint32_t OFF_B0 = (MODE == 1) ? 32768u : 16384u;     // Bh
    constexpr uint32_t OFF_B1 = 49152;                             // Bl (linear only)
    constexpr uint32_t STAGE  = (MODE == 1) ? 65536u : 81920u;

    extern __shared__ char smraw[];
    const uint32_t sraw = smem_u32(smraw);
    const uint32_t sb   = (sraw + 1023u) & ~1023u;

    const int tid  = threadIdx.x;
    const int wid  = tid >> 5;
    const int lane = tid & 31;
    const int wm   = wid & 1;
    const int wn   = wid >> 1;
    const int bm   = blockIdx.y * BM;
    const int bn   = blockIdx.x * BN;

    const __half* __restrict__ Ah = (MODE == 1) ? g_Ah : g_Xh;
    const __half* __restrict__ Al = (MODE == 1) ? g_Al : (const __half*)nullptr;
    const __half* __restrict__ Bh = (MODE == 1)
        ? g_Rh + (size_t)(bm >> 10) * EMBED * EMBED : g_Wh;
    const __half* __restrict__ Bl = (MODE == 1) ? (const __half*)nullptr : g_Wl;

    const int k16   = tid & 7;     // 16B column within 128B row
    const int rbase = tid >> 3;    // 0..31

    float acc[4][8][4];
#pragma unroll
    for (int i = 0; i < 4; ++i)
#pragma unroll
        for (int j = 0; j < 8; ++j)
#pragma unroll
            for (int q = 0; q < 4; ++q) acc[i][j][q] = 0.0f;

    auto issue = [&](int c, int stage) {
        const uint32_t st = sb + (uint32_t)stage * STAGE;
        const size_t kofs = (size_t)c * BK + k16 * 8;
#pragma unroll
        for (int i = 0; i < 4; ++i) {
            const int row = rbase + i * 32;                       // 0..127
            const uint32_t d = swz((uint32_t)(row * 128 + k16 * 16));
            cpasync16(st + OFF_A0 + d, Ah + (size_t)(bm + row) * EMBED + kofs);
            if (MODE == 1)
                cpasync16(st + OFF_A1 + d, Al + (size_t)(bm + row) * EMBED + kofs);
        }
#pragma unroll
        for (int i = 0; i < 8; ++i) {
            const int row = rbase + i * 32;                       // 0..255
            const uint32_t d = swz((uint32_t)(row * 128 + k16 * 16));
            cpasync16(st + OFF_B0 + d, Bh + (size_t)(bn + row) * EMBED + kofs);
            if (MODE == 0)
                cpasync16(st + OFF_B1 + d, Bl + (size_t)(bn + row) * EMBED + kofs);
        }
    };

    issue(0, 0);
    CP_COMMIT();
    CP_WAIT0();
    __syncthreads();

#pragma unroll 1
    for (int c = 0; c < NCHUNK; ++c) {
        const uint32_t st = sb + (uint32_t)(c & 1) * STAGE;
        const bool more = (c + 1 < NCHUNK);
        if (more) {
            issue(c + 1, (c + 1) & 1);
            CP_COMMIT();
        }
#pragma unroll
        for (int ks = 0; ks < 4; ++ks) {
            uint32_t b0[16], b1[16];
#pragma unroll
            for (int np = 0; np < 4; ++np) {
                const int rB = wn * 64 + np * 16 + (lane & 7) + ((lane >> 4) & 1) * 8;
                const uint32_t off = swz((uint32_t)(rB * 128 + ks * 32 + ((lane >> 3) & 1) * 16));
                ldsm4(b0[np * 4 + 0], b0[np * 4 + 1], b0[np * 4 + 2], b0[np * 4 + 3],
                      st + OFF_B0 + off);
                if (MODE == 0)
                    ldsm4(b1[np * 4 + 0], b1[np * 4 + 1], b1[np * 4 + 2], b1[np * 4 + 3],
                          st + OFF_B1 + off);
            }
#pragma unroll
            for (int mf = 0; mf < 4; ++mf) {
                const int rA = wm * 64 + mf * 16 + (lane & 15);
                const uint32_t off = swz((uint32_t)(rA * 128 + ks * 32 + (lane >> 4) * 16));
                uint32_t a0[4], a1[4];
                ldsm4(a0[0], a0[1], a0[2], a0[3], st + OFF_A0 + off);
                if (MODE == 1)
                    ldsm4(a1[0], a1[1], a1[2], a1[3], st + OFF_A1 + off);
#pragma unroll
                for (int nf = 0; nf < 8; ++nf) {
                    const uint32_t* bp0 = &b0[(nf >> 1) * 4 + (nf & 1) * 2];
                    if (MODE == 0) {
                        const uint32_t* bp1 = &b1[(nf >> 1) * 4 + (nf & 1) * 2];
                        mma16816(acc[mf][nf], a0, bp0);
                        mma16816(acc[mf][nf], a0, bp1);
                    } else {
                        mma16816(acc[mf][nf], a0, bp0);
                        mma16816(acc[mf][nf], a1, bp0);
                    }
                }
            }
        }
        if (more) CP_WAIT0();
        __syncthreads();
    }

    // ---- epilogue ----
    if (MODE == 0) {
        constexpr float INV = 1.0f / 256.0f;
#pragma unroll
        for (int nf = 0; nf < 8; ++nf) {
            const int col = bn + wn * 64 + nf * 8 + (lane & 3) * 2;
            const float b0 = bias[col], b1 = bias[col + 1];
#pragma unroll
            for (int mf = 0; mf < 4; ++mf) {
                const int row = bm + wm * 64 + mf * 16 + (lane >> 2);
                float2 v0 = make_float2(acc[mf][nf][0] * INV + b0, acc[mf][nf][1] * INV + b1);
                float2 v1 = make_float2(acc[mf][nf][2] * INV + b0, acc[mf][nf][3] * INV + b1);
                *reinterpret_cast<float2*>(out + (size_t)row * OUTF + col)       = v0;
                *reinterpret_cast<float2*>(out + (size_t)(row + 8) * OUTF + col) = v1;
            }
        }
    } else {
        const float s = scales[bm >> 10];   // W' = s * acc  (acc already carries the 256x)
#pragma unroll
        for (int nf = 0; nf < 8; ++nf) {
            const int col = bn + wn * 64 + nf * 8 + (lane & 3) * 2;
#pragma unroll
            for (int mf = 0; mf < 4; ++mf) {
                const int row = bm + wm * 64 + mf * 16 + (lane >> 2);
                float v0 = acc[mf][nf][0] * s, v1 = acc[mf][nf][1] * s;
                float v2 = acc[mf][nf][2] * s, v3 = acc[mf][nf][3] * s;
                __half h0, h1, h2, h3, l0, l1, l2, l3;
                split1(v0, h0, l0); split1(v1, h1, l1);
                split1(v2, h2, l2); split1(v3, h3, l3);
                size_t g0 = (size_t)row * EMBED + col;
                size_t g1 = (size_t)(row + 8) * EMBED + col;
                *reinterpret_cast<uint32_t*>(g_Wh + g0) = pack2(h0, h1);
                *reinterpret_cast<uint32_t*>(g_Wl + g0) = pack2(l0, l1);
                *reinterpret_cast<uint32_t*>(g_Wh + g1) = pack2(h2, h3);
                *reinterpret_cast<uint32_t*>(g_Wl + g1) = pack2(l2, l3);
            }
        }
    }
}

// ---------------------------------------------------------------------------
// Launch. Inputs: x, codewords, indices, rotations, scales, bias.
// ---------------------------------------------------------------------------
extern "C" void kernel_launch(void* const* d_in, const int* in_sizes, int n_in,
                              void* d_out, int out_size)
{
    const float* x         = (const float*)d_in[0];
    const float* codewords = (const float*)d_in[1];
    const int*   indices   = (const int*)  d_in[2];
    const float* rotations = (const float*)d_in[3];
    const float* scales    = (const float*)d_in[4];
    const float* bias      = (const float*)d_in[5];
    float*       out       = (float*)d_out;

    const int M = in_sizes[0] / EMBED;   // 8192

    cudaFuncSetAttribute(gemm_kernel<0>, cudaFuncAttributeMaxDynamicSharedMemorySize,
                         2 * 81920 + 1024);
    cudaFuncSetAttribute(gemm_kernel<1>, cudaFuncAttributeMaxDynamicSharedMemorySize,
                         2 * 65536 + 1024);

    // prep
    conv_x_kernel<<<(size_t)M * EMBED / 4096, NT>>>(x);
    gather_split_kernel<<<NTILES * RPT, NT>>>(codewords, indices);
    transpose_kernel<<<dim3(EMBED / 128, EMBED / 32, NTILES), NT>>>(rotations);

    // decode: W[4096 x 4096] (stored *256, split fp16)
    gemm_kernel<1><<<dim3(EMBED / BN, (NTILES * RPT) / BM), NT, 2 * 65536 + 1024>>>(
        nullptr, nullptr, scales);

    // linear: out[8192 x 4096]
    gemm_kernel<0><<<dim3(OUTF / BN, M / BM), NT, 2 * 81920 + 1024>>>(
        bias, out, nullptr);
}

// round 6
// speedup vs baseline: 4.5681x; 1.0467x over previous
#include <cuda_runtime.h>
#include <cuda_fp16.h>
#include <cstdint>
#include <cstddef>

// ---------------- problem constants ----------------
#define EMBED   4096
#define RPT     1024
#define NTILES  4
#define OUTF    4096
#define MTOK    8192            // B*S tokens

// ---------------- GEMM tiling ----------------
#define BK 64                   // 64 fp16 = 128B rows -> SW128 swizzle
#define NCHUNK (EMBED / BK)     // 64
#define NT 256
#define NSTAGE 3
#define STAGE_BYTES 65536u      // 64KB per stage (both modes)
#define SMEM_DYN (NSTAGE * STAGE_BYTES + 1024)

// ---------------- device scratch (fp16) ----------------
__device__ __half g_Xh[(size_t)MTOK * EMBED];             // x rounded fp16 (64MB)
__device__ __half g_Ah[(size_t)OUTF * EMBED];             // gathered cw*256 hi (32MB)
__device__ __half g_Al[(size_t)OUTF * EMBED];             // gathered cw*256 lo
__device__ __half g_Rh[(size_t)NTILES * EMBED * EMBED];   // R^T single fp16 (128MB)
__device__ __half g_Wh[(size_t)OUTF * EMBED];             // decoded W*256 hi
__device__ __half g_Wl[(size_t)OUTF * EMBED];             // decoded W*256 lo

// ---------------- helpers ----------------
__device__ __forceinline__ uint32_t smem_u32(const void* p) {
    uint32_t a;
    asm("{ .reg .u64 t; cvta.to.shared.u64 t, %1; cvt.u32.u64 %0, t; }" : "=r"(a) : "l"(p));
    return a;
}
__device__ __forceinline__ uint32_t swz(uint32_t b) { return b ^ ((b >> 3) & 0x70); }

__device__ __forceinline__ void ldsm4(uint32_t& r0, uint32_t& r1, uint32_t& r2, uint32_t& r3,
                                      uint32_t addr) {
    asm volatile("ldmatrix.sync.aligned.m8n8.x4.shared.b16 {%0,%1,%2,%3}, [%4];"
                 : "=r"(r0), "=r"(r1), "=r"(r2), "=r"(r3) : "r"(addr));
}
__device__ __forceinline__ void mma16816(float* c, const uint32_t* a, const uint32_t* b) {
    asm volatile(
        "mma.sync.aligned.m16n8k16.row.col.f32.f16.f16.f32 "
        "{%0,%1,%2,%3}, {%4,%5,%6,%7}, {%8,%9}, {%0,%1,%2,%3};"
        : "+f"(c[0]), "+f"(c[1]), "+f"(c[2]), "+f"(c[3])
        : "r"(a[0]), "r"(a[1]), "r"(a[2]), "r"(a[3]), "r"(b[0]), "r"(b[1]));
}
__device__ __forceinline__ void cpasync16(uint32_t dst, const void* src) {
    uint64_t g;
    asm("cvta.to.global.u64 %0, %1;" : "=l"(g) : "l"(src));
    asm volatile("cp.async.cg.shared.global [%0], [%1], 16;" :: "r"(dst), "l"(g));
}
#define CP_COMMIT() asm volatile("cp.async.commit_group;" ::: "memory")
#define CP_WAIT1()  asm volatile("cp.async.wait_group 1;" ::: "memory")

__device__ __forceinline__ uint32_t pack2(__half a, __half b) {
    return (uint32_t)__half_as_ushort(a) | ((uint32_t)__half_as_ushort(b) << 16);
}
__device__ __forceinline__ void split1(float v, __half& h, __half& l) {
    h = __float2half_rn(v);
    l = __float2half_rn(v - __half2float(h));
}
__device__ __forceinline__ bool indices_are_i64(const int* __restrict__ p) {
    bool is64 = true;
#pragma unroll
    for (int i = 0; i < 8; ++i) is64 = is64 && (p[2 * i + 1] == 0);
    return is64;
}

// ---------------------------------------------------------------------------
// Prep 1: x -> g_Xh (single fp16)
// ---------------------------------------------------------------------------
__global__ __launch_bounds__(NT)
void conv_x_kernel(const float* __restrict__ x)
{
#pragma unroll
    for (int j = 0; j < 4; ++j) {
        size_t f4 = (size_t)blockIdx.x * 1024 + threadIdx.x + j * 256;
        float4 v = *reinterpret_cast<const float4*>(x + f4 * 4);
        uint2 h;
        h.x = pack2(__float2half_rn(v.x), __float2half_rn(v.y));
        h.y = pack2(__float2half_rn(v.z), __float2half_rn(v.w));
        *reinterpret_cast<uint2*>(g_Xh + f4 * 4) = h;
    }
}

// ---------------------------------------------------------------------------
// Prep 2: gather + scale(256) + split codewords -> g_Ah/g_Al
// ---------------------------------------------------------------------------
__global__ __launch_bounds__(NT)
void gather_split_kernel(const float* __restrict__ codewords,
                         const int*   __restrict__ idx_raw)
{
    const int b = blockIdx.x;
    const bool is64 = indices_are_i64(idx_raw);
    const int cidx = is64 ? idx_raw[2 * b] : idx_raw[b];
    const float* __restrict__ src = codewords + (size_t)cidx * EMBED;
#pragma unroll
    for (int j = 0; j < 4; ++j) {
        int e4 = threadIdx.x + j * 256;
        float4 v = *reinterpret_cast<const float4*>(src + e4 * 4);
        __half h0, h1, h2, h3, l0, l1, l2, l3;
        split1(v.x * 256.0f, h0, l0); split1(v.y * 256.0f, h1, l1);
        split1(v.z * 256.0f, h2, l2); split1(v.w * 256.0f, h3, l3);
        size_t o = (size_t)b * EMBED + e4 * 4;
        *reinterpret_cast<uint2*>(g_Ah + o) = make_uint2(pack2(h0, h1), pack2(h2, h3));
        *reinterpret_cast<uint2*>(g_Al + o) = make_uint2(pack2(l0, l1), pack2(l2, l3));
    }
}

// ---------------------------------------------------------------------------
// Prep 3: transpose rotations: R[t][d][e] -> g_Rh [t][e][d] single fp16
// ---------------------------------------------------------------------------
__global__ __launch_bounds__(NT)
void transpose_kernel(const float* __restrict__ rot)
{
    __shared__ float sm[32][132];
    const int xb = blockIdx.x;   // e block (128)
    const int yb = blockIdx.y;   // d block (32)
    const int t  = blockIdx.z;
    const int tid = threadIdx.x;

#pragma unroll
    for (int p = 0; p < 4; ++p) {
        int dd = p * 8 + (tid >> 5);
        int e4 = (tid & 31);
        float4 v = *reinterpret_cast<const float4*>(
            rot + ((size_t)t * EMBED + yb * 32 + dd) * EMBED + xb * 128 + e4 * 4);
        *reinterpret_cast<float4*>(&sm[dd][e4 * 4]) = v;
    }
    __syncthreads();

#pragma unroll
    for (int p = 0; p < 8; ++p) {
        int e  = p * 16 + (tid >> 4);
        int dp = tid & 15;
        __half h0 = __float2half_rn(sm[2 * dp][e]);
        __half h1 = __float2half_rn(sm[2 * dp + 1][e]);
        size_t o = (size_t)t * EMBED * EMBED + (size_t)(xb * 128 + e) * EMBED + yb * 32 + 2 * dp;
        *reinterpret_cast<uint32_t*>(g_Rh + o) = pack2(h0, h1);
    }
}

// ---------------------------------------------------------------------------
// Unified 2-term GEMM, 3-stage cp.async pipeline (wait_group 1).
// MODE 0 (linear): BM=256 (A = Xh single), BN=128 (B = Wh+Wl split).
//                  out = C/256 + bias
// MODE 1 (decode): BM=128 (A = Ah+Al split), BN=256 (B = Rh single).
//                  g_W = split(C * scales[t])
// 8 warps, warp tile 64x64.
// ---------------------------------------------------------------------------
template<int MODE>
__global__ __launch_bounds__(NT, 1)
void gemm_kernel(const float* __restrict__ bias, float* __restrict__ out,
                 const float* __restrict__ scales)
{
    constexpr int BMc = (MODE == 1) ? 128 : 256;
    constexpr int BNc = (MODE == 1) ? 256 : 128;
    // stage layout (64KB both modes)
    constexpr uint32_t OFF_A0 = 0;
    constexpr uint32_t OFF_A1 = 16384;                            // decode only
    constexpr uint32_t OFF_B0 = 32768;
    constexpr uint32_t OFF_B1 = 49152;                            // linear only

    extern __shared__ char smraw[];
    const uint32_t sraw = smem_u32(smraw);
    const uint32_t sb   = (sraw + 1023u) & ~1023u;

    const int tid  = threadIdx.x;
    const int wid  = tid >> 5;
    const int lane = tid & 31;
    const int wm   = (MODE == 1) ? (wid & 1) : (wid & 3);
    const int wn   = (MODE == 1) ? (wid >> 1) : (wid >> 2);
    const int bm   = blockIdx.y * BMc;
    const int bn   = blockIdx.x * BNc;

    const __half* __restrict__ Ah = (MODE == 1) ? g_Ah : g_Xh;
    const __half* __restrict__ Al = (MODE == 1) ? g_Al : (const __half*)nullptr;
    const __half* __restrict__ Bh = (MODE == 1)
        ? g_Rh + (size_t)(bm >> 10) * EMBED * EMBED : g_Wh;
    const __half* __restrict__ Bl = (MODE == 1) ? (const __half*)nullptr : g_Wl;

    const int k16   = tid & 7;     // 16B column within 128B row
    const int rbase = tid >> 3;    // 0..31

    float acc[4][8][4];
#pragma unroll
    for (int i = 0; i < 4; ++i)
#pragma unroll
        for (int j = 0; j < 8; ++j)
#pragma unroll
            for (int q = 0; q < 4; ++q) acc[i][j][q] = 0.0f;

    auto issue = [&](int c, int stage) {
        const uint32_t st = sb + (uint32_t)stage * STAGE_BYTES;
        const size_t kofs = (size_t)c * BK + k16 * 8;
#pragma unroll
        for (int i = 0; i < BMc / 32; ++i) {
            const int row = rbase + i * 32;
            const uint32_t d = swz((uint32_t)(row * 128 + k16 * 16));
            cpasync16(st + OFF_A0 + d, Ah + (size_t)(bm + row) * EMBED + kofs);
            if (MODE == 1)
                cpasync16(st + OFF_A1 + d, Al + (size_t)(bm + row) * EMBED + kofs);
        }
#pragma unroll
        for (int i = 0; i < BNc / 32; ++i) {
            const int row = rbase + i * 32;
            const uint32_t d = swz((uint32_t)(row * 128 + k16 * 16));
            cpasync16(st + OFF_B0 + d, Bh + (size_t)(bn + row) * EMBED + kofs);
            if (MODE == 0)
                cpasync16(st + OFF_B1 + d, Bl + (size_t)(bn + row) * EMBED + kofs);
        }
    };

    // prologue: stages 0,1 in flight
    issue(0, 0);
    CP_COMMIT();
    issue(1, 1);
    CP_COMMIT();

    int stage = 0;
#pragma unroll 1
    for (int c = 0; c < NCHUNK; ++c) {
        CP_WAIT1();              // group c retired; group c+1 may be in flight
        __syncthreads();         // all warps done with stage being overwritten
        if (c + 2 < NCHUNK) issue(c + 2, (stage + 2) % NSTAGE);
        CP_COMMIT();             // always commit (keeps group counting sound)

        const uint32_t st = sb + (uint32_t)stage * STAGE_BYTES;
#pragma unroll
        for (int ks = 0; ks < 4; ++ks) {
            uint32_t b0[16], b1[16];
#pragma unroll
            for (int np = 0; np < 4; ++np) {
                const int rB = wn * 64 + np * 16 + (lane & 7) + ((lane >> 4) & 1) * 8;
                const uint32_t off = swz((uint32_t)(rB * 128 + ks * 32 + ((lane >> 3) & 1) * 16));
                ldsm4(b0[np * 4 + 0], b0[np * 4 + 1], b0[np * 4 + 2], b0[np * 4 + 3],
                      st + OFF_B0 + off);
                if (MODE == 0)
                    ldsm4(b1[np * 4 + 0], b1[np * 4 + 1], b1[np * 4 + 2], b1[np * 4 + 3],
                          st + OFF_B1 + off);
            }
#pragma unroll
            for (int mf = 0; mf < 4; ++mf) {
                const int rA = wm * 64 + mf * 16 + (lane & 15);
                const uint32_t off = swz((uint32_t)(rA * 128 + ks * 32 + (lane >> 4) * 16));
                uint32_t a0[4], a1[4];
                ldsm4(a0[0], a0[1], a0[2], a0[3], st + OFF_A0 + off);
                if (MODE == 1)
                    ldsm4(a1[0], a1[1], a1[2], a1[3], st + OFF_A1 + off);
#pragma unroll
                for (int nf = 0; nf < 8; ++nf) {
                    const uint32_t* bp0 = &b0[(nf >> 1) * 4 + (nf & 1) * 2];
                    if (MODE == 0) {
                        const uint32_t* bp1 = &b1[(nf >> 1) * 4 + (nf & 1) * 2];
                        mma16816(acc[mf][nf], a0, bp0);
                        mma16816(acc[mf][nf], a0, bp1);
                    } else {
                        mma16816(acc[mf][nf], a0, bp0);
                        mma16816(acc[mf][nf], a1, bp0);
                    }
                }
            }
        }
        stage = (stage + 1) % NSTAGE;
    }

    // ---- epilogue ----
    if (MODE == 0) {
        constexpr float INV = 1.0f / 256.0f;
#pragma unroll
        for (int nf = 0; nf < 8; ++nf) {
            const int col = bn + wn * 64 + nf * 8 + (lane & 3) * 2;
            const float b0 = bias[col], b1 = bias[col + 1];
#pragma unroll
            for (int mf = 0; mf < 4; ++mf) {
                const int row = bm + wm * 64 + mf * 16 + (lane >> 2);
                float2 v0 = make_float2(acc[mf][nf][0] * INV + b0, acc[mf][nf][1] * INV + b1);
                float2 v1 = make_float2(acc[mf][nf][2] * INV + b0, acc[mf][nf][3] * INV + b1);
                *reinterpret_cast<float2*>(out + (size_t)row * OUTF + col)       = v0;
                *reinterpret_cast<float2*>(out + (size_t)(row + 8) * OUTF + col) = v1;
            }
        }
    } else {
        const float s = scales[bm >> 10];
#pragma unroll
        for (int nf = 0; nf < 8; ++nf) {
            const int col = bn + wn * 64 + nf * 8 + (lane & 3) * 2;
#pragma unroll
            for (int mf = 0; mf < 4; ++mf) {
                const int row = bm + wm * 64 + mf * 16 + (lane >> 2);
                float v0 = acc[mf][nf][0] * s, v1 = acc[mf][nf][1] * s;
                float v2 = acc[mf][nf][2] * s, v3 = acc[mf][nf][3] * s;
                __half h0, h1, h2, h3, l0, l1, l2, l3;
                split1(v0, h0, l0); split1(v1, h1, l1);
                split1(v2, h2, l2); split1(v3, h3, l3);
                size_t g0 = (size_t)row * EMBED + col;
                size_t g1 = (size_t)(row + 8) * EMBED + col;
                *reinterpret_cast<uint32_t*>(g_Wh + g0) = pack2(h0, h1);
                *reinterpret_cast<uint32_t*>(g_Wl + g0) = pack2(l0, l1);
                *reinterpret_cast<uint32_t*>(g_Wh + g1) = pack2(h2, h3);
                *reinterpret_cast<uint32_t*>(g_Wl + g1) = pack2(l2, l3);
            }
        }
    }
}

// ---------------------------------------------------------------------------
// Launch. Inputs: x, codewords, indices, rotations, scales, bias.
// ---------------------------------------------------------------------------
extern "C" void kernel_launch(void* const* d_in, const int* in_sizes, int n_in,
                              void* d_out, int out_size)
{
    const float* x         = (const float*)d_in[0];
    const float* codewords = (const float*)d_in[1];
    const int*   indices   = (const int*)  d_in[2];
    const float* rotations = (const float*)d_in[3];
    const float* scales    = (const float*)d_in[4];
    const float* bias      = (const float*)d_in[5];
    float*       out       = (float*)d_out;

    const int M = in_sizes[0] / EMBED;   // 8192

    cudaFuncSetAttribute(gemm_kernel<0>, cudaFuncAttributeMaxDynamicSharedMemorySize, SMEM_DYN);
    cudaFuncSetAttribute(gemm_kernel<1>, cudaFuncAttributeMaxDynamicSharedMemorySize, SMEM_DYN);

    // prep
    conv_x_kernel<<<(size_t)M * EMBED / 4096, NT>>>(x);
    gather_split_kernel<<<NTILES * RPT, NT>>>(codewords, indices);
    transpose_kernel<<<dim3(EMBED / 128, EMBED / 32, NTILES), NT>>>(rotations);

    // decode: W[4096 x 4096] = (cw*256 split) @ R^T, stored *256 split fp16
    gemm_kernel<1><<<dim3(EMBED / 256, (NTILES * RPT) / 128), NT, SMEM_DYN>>>(
        nullptr, nullptr, scales);

    // linear: out[8192 x 4096] = x @ (W*256 split)^T / 256 + bias
    gemm_kernel<0><<<dim3(OUTF / 128, M / 256), NT, SMEM_DYN>>>(
        bias, out, nullptr);
}

// round 7
// speedup vs baseline: 5.2119x; 1.1409x over previous
#include <cuda_runtime.h>
#include <cuda_fp16.h>
#include <cstdint>
#include <cstddef>

// ---------------- problem constants ----------------
#define EMBED   4096
#define RPT     1024
#define NTILES  4
#define OUTF    4096
#define MTOK    8192            // B*S tokens

// ---------------- GEMM tiling ----------------
#define BK 64                   // 64 fp16 = 128B rows -> SW128 swizzle
#define NCHUNK (EMBED / BK)     // 64
#define NTG 512                 // GEMM threads (16 warps)
#define NT  256                 // prep threads
#define NSTAGE 3

// ---------------- device scratch (fp16) ----------------
__device__ __half g_Xh[(size_t)MTOK * EMBED];             // x rounded fp16 (64MB)
__device__ __half g_Ah[(size_t)OUTF * EMBED];             // gathered cw fp16 (32MB)
__device__ __half g_Rh[(size_t)NTILES * EMBED * EMBED];   // R^T single fp16 (128MB)
__device__ __half g_Wh[(size_t)OUTF * EMBED];             // decoded W*256 hi
__device__ __half g_Wl[(size_t)OUTF * EMBED];             // decoded W*256 lo

// ---------------- helpers ----------------
__device__ __forceinline__ uint32_t smem_u32(const void* p) {
    uint32_t a;
    asm("{ .reg .u64 t; cvta.to.shared.u64 t, %1; cvt.u32.u64 %0, t; }" : "=r"(a) : "l"(p));
    return a;
}
__device__ __forceinline__ uint32_t swz(uint32_t b) { return b ^ ((b >> 3) & 0x70); }

__device__ __forceinline__ void ldsm4(uint32_t& r0, uint32_t& r1, uint32_t& r2, uint32_t& r3,
                                      uint32_t addr) {
    asm volatile("ldmatrix.sync.aligned.m8n8.x4.shared.b16 {%0,%1,%2,%3}, [%4];"
                 : "=r"(r0), "=r"(r1), "=r"(r2), "=r"(r3) : "r"(addr));
}
__device__ __forceinline__ void mma16816(float* c, const uint32_t* a, const uint32_t* b) {
    asm volatile(
        "mma.sync.aligned.m16n8k16.row.col.f32.f16.f16.f32 "
        "{%0,%1,%2,%3}, {%4,%5,%6,%7}, {%8,%9}, {%0,%1,%2,%3};"
        : "+f"(c[0]), "+f"(c[1]), "+f"(c[2]), "+f"(c[3])
        : "r"(a[0]), "r"(a[1]), "r"(a[2]), "r"(a[3]), "r"(b[0]), "r"(b[1]));
}
__device__ __forceinline__ void cpasync16(uint32_t dst, const void* src) {
    uint64_t g;
    asm("cvta.to.global.u64 %0, %1;" : "=l"(g) : "l"(src));
    asm volatile("cp.async.cg.shared.global [%0], [%1], 16;" :: "r"(dst), "l"(g));
}
#define CP_COMMIT() asm volatile("cp.async.commit_group;" ::: "memory")
#define CP_WAIT1()  asm volatile("cp.async.wait_group 1;" ::: "memory")

__device__ __forceinline__ uint32_t pack2(__half a, __half b) {
    return (uint32_t)__half_as_ushort(a) | ((uint32_t)__half_as_ushort(b) << 16);
}
__device__ __forceinline__ void split1(float v, __half& h, __half& l) {
    h = __float2half_rn(v);
    l = __float2half_rn(v - __half2float(h));
}
__device__ __forceinline__ bool indices_are_i64(const int* __restrict__ p) {
    bool is64 = true;
#pragma unroll
    for (int i = 0; i < 8; ++i) is64 = is64 && (p[2 * i + 1] == 0);
    return is64;
}

// ---------------------------------------------------------------------------
// Prep 1: x -> g_Xh (single fp16)
// ---------------------------------------------------------------------------
__global__ __launch_bounds__(NT)
void conv_x_kernel(const float* __restrict__ x)
{
#pragma unroll
    for (int j = 0; j < 4; ++j) {
        size_t f4 = (size_t)blockIdx.x * 1024 + threadIdx.x + j * 256;
        float4 v = *reinterpret_cast<const float4*>(x + f4 * 4);
        uint2 h;
        h.x = pack2(__float2half_rn(v.x), __float2half_rn(v.y));
        h.y = pack2(__float2half_rn(v.z), __float2half_rn(v.w));
        *reinterpret_cast<uint2*>(g_Xh + f4 * 4) = h;
    }
}

// ---------------------------------------------------------------------------
// Prep 2: gather + round codewords -> g_Ah (single fp16)
// ---------------------------------------------------------------------------
__global__ __launch_bounds__(NT)
void gather_kernel(const float* __restrict__ codewords,
                   const int*   __restrict__ idx_raw)
{
    const int b = blockIdx.x;
    const bool is64 = indices_are_i64(idx_raw);
    const int cidx = is64 ? idx_raw[2 * b] : idx_raw[b];
    const float* __restrict__ src = codewords + (size_t)cidx * EMBED;
#pragma unroll
    for (int j = 0; j < 4; ++j) {
        int e4 = threadIdx.x + j * 256;
        float4 v = *reinterpret_cast<const float4*>(src + e4 * 4);
        uint2 h;
        h.x = pack2(__float2half_rn(v.x), __float2half_rn(v.y));
        h.y = pack2(__float2half_rn(v.z), __float2half_rn(v.w));
        *reinterpret_cast<uint2*>(g_Ah + (size_t)b * EMBED + e4 * 4) = h;
    }
}

// ---------------------------------------------------------------------------
// Prep 3: transpose rotations: R[t][d][e] -> g_Rh [t][e][d] single fp16
// ---------------------------------------------------------------------------
__global__ __launch_bounds__(NT)
void transpose_kernel(const float* __restrict__ rot)
{
    __shared__ float sm[32][132];
    const int xb = blockIdx.x;   // e block (128)
    const int yb = blockIdx.y;   // d block (32)
    const int t  = blockIdx.z;
    const int tid = threadIdx.x;

#pragma unroll
    for (int p = 0; p < 4; ++p) {
        int dd = p * 8 + (tid >> 5);
        int e4 = (tid & 31);
        float4 v = *reinterpret_cast<const float4*>(
            rot + ((size_t)t * EMBED + yb * 32 + dd) * EMBED + xb * 128 + e4 * 4);
        *reinterpret_cast<float4*>(&sm[dd][e4 * 4]) = v;
    }
    __syncthreads();

#pragma unroll
    for (int p = 0; p < 8; ++p) {
        int e  = p * 16 + (tid >> 4);
        int dp = tid & 15;
        __half h0 = __float2half_rn(sm[2 * dp][e]);
        __half h1 = __float2half_rn(sm[2 * dp + 1][e]);
        size_t o = (size_t)t * EMBED * EMBED + (size_t)(xb * 128 + e) * EMBED + yb * 32 + 2 * dp;
        *reinterpret_cast<uint32_t*>(g_Rh + o) = pack2(h0, h1);
    }
}

// ---------------------------------------------------------------------------
// GEMMs, 512 threads (16 warps), 3-stage cp.async pipeline (wait_group 1).
// MODE 0 (linear): CTA 256x128, warp 64x32. A = Xh (single), B = Wh+Wl (split).
//                  out = C/256 + bias
// MODE 1 (decode): CTA 128x256, warp 32x64. A = Ah (single), B = Rh (single).
//                  g_W = split(C * scales[t] * 256)
// ---------------------------------------------------------------------------
template<int MODE>
__global__ __launch_bounds__(NTG, 1)
void gemm_kernel(const float* __restrict__ bias, float* __restrict__ out,
                 const float* __restrict__ scales)
{
    constexpr int BMc = (MODE == 1) ? 128 : 256;
    constexpr int BNc = (MODE == 1) ? 256 : 128;
    constexpr int NMF = (MODE == 1) ? 2 : 4;      // 16-row frags per warp (M)
    constexpr int NNF = (MODE == 1) ? 8 : 4;      // 8-col frags per warp (N)
    constexpr int WMH = NMF * 16;                 // warp tile M
    constexpr int WNH = NNF * 8;                  // warp tile N
    // stage layout
    constexpr uint32_t OFF_A0 = 0;
    constexpr uint32_t OFF_B0 = (uint32_t)BMc * 128;                   // after A
    constexpr uint32_t OFF_B1 = OFF_B0 + (uint32_t)BNc * 128;          // linear only
    constexpr uint32_t STAGE  = (MODE == 1)
        ? (uint32_t)(BMc + BNc) * 128            // 48KB
        : (uint32_t)(BMc + 2 * BNc) * 128;       // 64KB

    extern __shared__ char smraw[];
    const uint32_t sraw = smem_u32(smraw);
    const uint32_t sb   = (sraw + 1023u) & ~1023u;

    const int tid  = threadIdx.x;
    const int wid  = tid >> 5;
    const int lane = tid & 31;
    const int wm   = wid & 3;        // 4 warps along M
    const int wn   = wid >> 2;       // 4 warps along N
    const int bm   = blockIdx.y * BMc;
    const int bn   = blockIdx.x * BNc;

    const __half* __restrict__ Ah = (MODE == 1) ? g_Ah : g_Xh;
    const __half* __restrict__ Bh = (MODE == 1)
        ? g_Rh + (size_t)(bm >> 10) * EMBED * EMBED : g_Wh;
    const __half* __restrict__ Bl = (MODE == 1) ? (const __half*)nullptr : g_Wl;

    const int k16   = tid & 7;      // 16B column within 128B row
    const int rbase = tid >> 3;     // 0..63

    float acc[NMF][NNF][4];
#pragma unroll
    for (int i = 0; i < NMF; ++i)
#pragma unroll
        for (int j = 0; j < NNF; ++j)
#pragma unroll
            for (int q = 0; q < 4; ++q) acc[i][j][q] = 0.0f;

    auto issue = [&](int c, int stage) {
        const uint32_t st = sb + (uint32_t)stage * STAGE;
        const size_t kofs = (size_t)c * BK + k16 * 8;
#pragma unroll
        for (int i = 0; i < BMc / 64; ++i) {
            const int row = rbase + i * 64;
            const uint32_t d = swz((uint32_t)(row * 128 + k16 * 16));
            cpasync16(st + OFF_A0 + d, Ah + (size_t)(bm + row) * EMBED + kofs);
        }
#pragma unroll
        for (int i = 0; i < BNc / 64; ++i) {
            const int row = rbase + i * 64;
            const uint32_t d = swz((uint32_t)(row * 128 + k16 * 16));
            cpasync16(st + OFF_B0 + d, Bh + (size_t)(bn + row) * EMBED + kofs);
            if (MODE == 0)
                cpasync16(st + OFF_B1 + d, Bl + (size_t)(bn + row) * EMBED + kofs);
        }
    };

    // prologue: stages 0,1 in flight
    issue(0, 0);
    CP_COMMIT();
    issue(1, 1);
    CP_COMMIT();

    int stage = 0;
#pragma unroll 1
    for (int c = 0; c < NCHUNK; ++c) {
        CP_WAIT1();              // group c retired; group c+1 may be in flight
        __syncthreads();         // all warps done reading the stage being overwritten
        if (c + 2 < NCHUNK) issue(c + 2, (stage + 2) % NSTAGE);
        CP_COMMIT();             // always commit (keeps group counting sound)

        const uint32_t st = sb + (uint32_t)stage * STAGE;
#pragma unroll
        for (int ks = 0; ks < 4; ++ks) {
            uint32_t b0[NNF * 2], b1[NNF * 2];
#pragma unroll
            for (int np = 0; np < NNF / 2; ++np) {
                const int rB = wn * WNH + np * 16 + (lane & 7) + ((lane >> 4) & 1) * 8;
                const uint32_t off = swz((uint32_t)(rB * 128 + ks * 32 + ((lane >> 3) & 1) * 16));
                ldsm4(b0[np * 4 + 0], b0[np * 4 + 1], b0[np * 4 + 2], b0[np * 4 + 3],
                      st + OFF_B0 + off);
                if (MODE == 0)
                    ldsm4(b1[np * 4 + 0], b1[np * 4 + 1], b1[np * 4 + 2], b1[np * 4 + 3],
                          st + OFF_B1 + off);
            }
#pragma unroll
            for (int mf = 0; mf < NMF; ++mf) {
                const int rA = wm * WMH + mf * 16 + (lane & 15);
                const uint32_t off = swz((uint32_t)(rA * 128 + ks * 32 + (lane >> 4) * 16));
                uint32_t a0[4];
                ldsm4(a0[0], a0[1], a0[2], a0[3], st + OFF_A0 + off);
#pragma unroll
                for (int nf = 0; nf < NNF; ++nf) {
                    const uint32_t* bp0 = &b0[(nf >> 1) * 4 + (nf & 1) * 2];
                    mma16816(acc[mf][nf], a0, bp0);
                    if (MODE == 0) {
                        const uint32_t* bp1 = &b1[(nf >> 1) * 4 + (nf & 1) * 2];
                        mma16816(acc[mf][nf], a0, bp1);
                    }
                }
            }
        }
        stage = (stage + 1) % NSTAGE;
    }

    // ---- epilogue ----
    if (MODE == 0) {
        constexpr float INV = 1.0f / 256.0f;
#pragma unroll
        for (int nf = 0; nf < NNF; ++nf) {
            const int col = bn + wn * WNH + nf * 8 + (lane & 3) * 2;
            const float b0 = bias[col], b1 = bias[col + 1];
#pragma unroll
            for (int mf = 0; mf < NMF; ++mf) {
                const int row = bm + wm * WMH + mf * 16 + (lane >> 2);
                float2 v0 = make_float2(acc[mf][nf][0] * INV + b0, acc[mf][nf][1] * INV + b1);
                float2 v1 = make_float2(acc[mf][nf][2] * INV + b0, acc[mf][nf][3] * INV + b1);
                *reinterpret_cast<float2*>(out + (size_t)row * OUTF + col)       = v0;
                *reinterpret_cast<float2*>(out + (size_t)(row + 8) * OUTF + col) = v1;
            }
        }
    } else {
        const float s = scales[bm >> 10] * 256.0f;
#pragma unroll
        for (int nf = 0; nf < NNF; ++nf) {
            const int col = bn + wn * WNH + nf * 8 + (lane & 3) * 2;
#pragma unroll
            for (int mf = 0; mf < NMF; ++mf) {
                const int row = bm + wm * WMH + mf * 16 + (lane >> 2);
                float v0 = acc[mf][nf][0] * s, v1 = acc[mf][nf][1] * s;
                float v2 = acc[mf][nf][2] * s, v3 = acc[mf][nf][3] * s;
                __half h0, h1, h2, h3, l0, l1, l2, l3;
                split1(v0, h0, l0); split1(v1, h1, l1);
                split1(v2, h2, l2); split1(v3, h3, l3);
                size_t g0 = (size_t)row * EMBED + col;
                size_t g1 = (size_t)(row + 8) * EMBED + col;
                *reinterpret_cast<uint32_t*>(g_Wh + g0) = pack2(h0, h1);
                *reinterpret_cast<uint32_t*>(g_Wl + g0) = pack2(l0, l1);
                *reinterpret_cast<uint32_t*>(g_Wh + g1) = pack2(h2, h3);
                *reinterpret_cast<uint32_t*>(g_Wl + g1) = pack2(l2, l3);
            }
        }
    }
}

// ---------------------------------------------------------------------------
// Launch. Inputs: x, codewords, indices, rotations, scales, bias.
// ---------------------------------------------------------------------------
extern "C" void kernel_launch(void* const* d_in, const int* in_sizes, int n_in,
                              void* d_out, int out_size)
{
    const float* x         = (const float*)d_in[0];
    const float* codewords = (const float*)d_in[1];
    const int*   indices   = (const int*)  d_in[2];
    const float* rotations = (const float*)d_in[3];
    const float* scales    = (const float*)d_in[4];
    const float* bias      = (const float*)d_in[5];
    float*       out       = (float*)d_out;

    const int M = in_sizes[0] / EMBED;   // 8192

    const int smem1 = NSTAGE * (128 + 256) * 128 + 1024;       // decode: 145KB
    const int smem0 = NSTAGE * (256 + 2 * 128) * 128 + 1024;   // linear: 193KB
    cudaFuncSetAttribute(gemm_kernel<0>, cudaFuncAttributeMaxDynamicSharedMemorySize, smem0);
    cudaFuncSetAttribute(gemm_kernel<1>, cudaFuncAttributeMaxDynamicSharedMemorySize, smem1);

    // prep
    conv_x_kernel<<<(size_t)M * EMBED / 4096, NT>>>(x);
    gather_kernel<<<NTILES * RPT, NT>>>(codewords, indices);
    transpose_kernel<<<dim3(EMBED / 128, EMBED / 32, NTILES), NT>>>(rotations);

    // decode: W[4096 x 4096] = cw @ R^T, stored *256 split fp16
    gemm_kernel<1><<<dim3(EMBED / 256, (NTILES * RPT) / 128), NTG, smem1>>>(
        nullptr, nullptr, scales);

    // linear: out[8192 x 4096] = x @ (W*256 split)^T / 256 + bias
    gemm_kernel<0><<<dim3(OUTF / 128, M / 256), NTG, smem0>>>(
        bias, out, nullptr);
}

// round 8
// speedup vs baseline: 7.8277x; 1.5019x over previous
#include <cuda_runtime.h>
#include <cuda_fp16.h>
#include <cstdint>
#include <cstddef>

// ---------------- problem constants ----------------
#define EMBED   4096
#define RPT     1024
#define NTILES  4
#define OUTF    4096
#define MTOK    8192            // B*S tokens

// ---------------- GEMM tiling ----------------
#define BK 64                   // 64 fp16 = 128B rows -> SW128 swizzle
#define NCHUNK (EMBED / BK)     // 64
#define NTG 512                 // GEMM threads (16 warps)
#define NT  256                 // prep threads
#define NSTAGE 4
#define STAGE_BYTES ((uint32_t)(128 + 256) * 128)   // 48KB (both modes)
#define SMEM_DYN (NSTAGE * STAGE_BYTES + 1024)      // 193KB

// ---------------- device scratch (fp16) ----------------
__device__ __half g_Xh[(size_t)MTOK * EMBED];             // x rounded fp16 (64MB)
__device__ __half g_Ah[(size_t)OUTF * EMBED];             // gathered cw fp16 (32MB)
__device__ __half g_Rh[(size_t)NTILES * EMBED * EMBED];   // R^T single fp16 (128MB)
__device__ __half g_Wh[(size_t)OUTF * EMBED];             // decoded W*256 fp16 (32MB)

// ---------------- helpers ----------------
__device__ __forceinline__ uint32_t smem_u32(const void* p) {
    uint32_t a;
    asm("{ .reg .u64 t; cvta.to.shared.u64 t, %1; cvt.u32.u64 %0, t; }" : "=r"(a) : "l"(p));
    return a;
}
__device__ __forceinline__ uint32_t swz(uint32_t b) { return b ^ ((b >> 3) & 0x70); }

__device__ __forceinline__ void ldsm4(uint32_t& r0, uint32_t& r1, uint32_t& r2, uint32_t& r3,
                                      uint32_t addr) {
    asm volatile("ldmatrix.sync.aligned.m8n8.x4.shared.b16 {%0,%1,%2,%3}, [%4];"
                 : "=r"(r0), "=r"(r1), "=r"(r2), "=r"(r3) : "r"(addr));
}
__device__ __forceinline__ void mma16816(float* c, const uint32_t* a, const uint32_t* b) {
    asm volatile(
        "mma.sync.aligned.m16n8k16.row.col.f32.f16.f16.f32 "
        "{%0,%1,%2,%3}, {%4,%5,%6,%7}, {%8,%9}, {%0,%1,%2,%3};"
        : "+f"(c[0]), "+f"(c[1]), "+f"(c[2]), "+f"(c[3])
        : "r"(a[0]), "r"(a[1]), "r"(a[2]), "r"(a[3]), "r"(b[0]), "r"(b[1]));
}
__device__ __forceinline__ void cpasync16(uint32_t dst, const void* src) {
    uint64_t g;
    asm("cvta.to.global.u64 %0, %1;" : "=l"(g) : "l"(src));
    asm volatile("cp.async.cg.shared.global [%0], [%1], 16;" :: "r"(dst), "l"(g));
}
#define CP_COMMIT() asm volatile("cp.async.commit_group;" ::: "memory")
#define CP_WAIT2()  asm volatile("cp.async.wait_group 2;" ::: "memory")

__device__ __forceinline__ uint32_t pack2(__half a, __half b) {
    return (uint32_t)__half_as_ushort(a) | ((uint32_t)__half_as_ushort(b) << 16);
}
__device__ __forceinline__ bool indices_are_i64(const int* __restrict__ p) {
    bool is64 = true;
#pragma unroll
    for (int i = 0; i < 8; ++i) is64 = is64 && (p[2 * i + 1] == 0);
    return is64;
}

// ---------------------------------------------------------------------------
// Prep 1: x -> g_Xh (single fp16)
// ---------------------------------------------------------------------------
__global__ __launch_bounds__(NT)
void conv_x_kernel(const float* __restrict__ x)
{
#pragma unroll
    for (int j = 0; j < 4; ++j) {
        size_t f4 = (size_t)blockIdx.x * 1024 + threadIdx.x + j * 256;
        float4 v = *reinterpret_cast<const float4*>(x + f4 * 4);
        uint2 h;
        h.x = pack2(__float2half_rn(v.x), __float2half_rn(v.y));
        h.y = pack2(__float2half_rn(v.z), __float2half_rn(v.w));
        *reinterpret_cast<uint2*>(g_Xh + f4 * 4) = h;
    }
}

// ---------------------------------------------------------------------------
// Prep 2: gather + round codewords -> g_Ah (single fp16)
// ---------------------------------------------------------------------------
__global__ __launch_bounds__(NT)
void gather_kernel(const float* __restrict__ codewords,
                   const int*   __restrict__ idx_raw)
{
    const int b = blockIdx.x;
    const bool is64 = indices_are_i64(idx_raw);
    const int cidx = is64 ? idx_raw[2 * b] : idx_raw[b];
    const float* __restrict__ src = codewords + (size_t)cidx * EMBED;
#pragma unroll
    for (int j = 0; j < 4; ++j) {
        int e4 = threadIdx.x + j * 256;
        float4 v = *reinterpret_cast<const float4*>(src + e4 * 4);
        uint2 h;
        h.x = pack2(__float2half_rn(v.x), __float2half_rn(v.y));
        h.y = pack2(__float2half_rn(v.z), __float2half_rn(v.w));
        *reinterpret_cast<uint2*>(g_Ah + (size_t)b * EMBED + e4 * 4) = h;
    }
}

// ---------------------------------------------------------------------------
// Prep 3: transpose rotations: R[t][d][e] -> g_Rh [t][e][d] single fp16
// ---------------------------------------------------------------------------
__global__ __launch_bounds__(NT)
void transpose_kernel(const float* __restrict__ rot)
{
    __shared__ float sm[32][132];
    const int xb = blockIdx.x;   // e block (128)
    const int yb = blockIdx.y;   // d block (32)
    const int t  = blockIdx.z;
    const int tid = threadIdx.x;

#pragma unroll
    for (int p = 0; p < 4; ++p) {
        int dd = p * 8 + (tid >> 5);
        int e4 = (tid & 31);
        float4 v = *reinterpret_cast<const float4*>(
            rot + ((size_t)t * EMBED + yb * 32 + dd) * EMBED + xb * 128 + e4 * 4);
        *reinterpret_cast<float4*>(&sm[dd][e4 * 4]) = v;
    }
    __syncthreads();

#pragma unroll
    for (int p = 0; p < 8; ++p) {
        int e  = p * 16 + (tid >> 4);
        int dp = tid & 15;
        __half h0 = __float2half_rn(sm[2 * dp][e]);
        __half h1 = __float2half_rn(sm[2 * dp + 1][e]);
        size_t o = (size_t)t * EMBED * EMBED + (size_t)(xb * 128 + e) * EMBED + yb * 32 + 2 * dp;
        *reinterpret_cast<uint32_t*>(g_Rh + o) = pack2(h0, h1);
    }
}

// ---------------------------------------------------------------------------
// Single-term fp16 GEMMs, 512 threads (16 warps), 4-stage cp.async pipeline.
// MODE 0 (linear): CTA 256x128, warp 64x32. A = Xh, B = Wh. out = C/256 + bias
// MODE 1 (decode): CTA 128x256, warp 32x64. A = Ah, B = Rh.
//                  g_Wh = fp16(C * scales[t] * 256)
// ---------------------------------------------------------------------------
template<int MODE>
__global__ __launch_bounds__(NTG, 1)
void gemm_kernel(const float* __restrict__ bias, float* __restrict__ out,
                 const float* __restrict__ scales)
{
    constexpr int BMc = (MODE == 1) ? 128 : 256;
    constexpr int BNc = (MODE == 1) ? 256 : 128;
    constexpr int NMF = (MODE == 1) ? 2 : 4;      // 16-row frags per warp (M)
    constexpr int NNF = (MODE == 1) ? 8 : 4;      // 8-col frags per warp (N)
    constexpr int WMH = NMF * 16;
    constexpr int WNH = NNF * 8;
    constexpr uint32_t OFF_A0 = 0;
    constexpr uint32_t OFF_B0 = (uint32_t)BMc * 128;

    extern __shared__ char smraw[];
    const uint32_t sraw = smem_u32(smraw);
    const uint32_t sb   = (sraw + 1023u) & ~1023u;

    const int tid  = threadIdx.x;
    const int wid  = tid >> 5;
    const int lane = tid & 31;
    const int wm   = wid & 3;        // 4 warps along M
    const int wn   = wid >> 2;       // 4 warps along N
    const int bm   = blockIdx.y * BMc;
    const int bn   = blockIdx.x * BNc;

    const __half* __restrict__ Ah = (MODE == 1) ? g_Ah : g_Xh;
    const __half* __restrict__ Bh = (MODE == 1)
        ? g_Rh + (size_t)(bm >> 10) * EMBED * EMBED : g_Wh;

    const int k16   = tid & 7;      // 16B column within 128B row
    const int rbase = tid >> 3;     // 0..63

    float acc[NMF][NNF][4];
#pragma unroll
    for (int i = 0; i < NMF; ++i)
#pragma unroll
        for (int j = 0; j < NNF; ++j)
#pragma unroll
            for (int q = 0; q < 4; ++q) acc[i][j][q] = 0.0f;

    auto issue = [&](int c, int stage) {
        const uint32_t st = sb + (uint32_t)stage * STAGE_BYTES;
        const size_t kofs = (size_t)c * BK + k16 * 8;
#pragma unroll
        for (int i = 0; i < BMc / 64; ++i) {
            const int row = rbase + i * 64;
            const uint32_t d = swz((uint32_t)(row * 128 + k16 * 16));
            cpasync16(st + OFF_A0 + d, Ah + (size_t)(bm + row) * EMBED + kofs);
        }
#pragma unroll
        for (int i = 0; i < BNc / 64; ++i) {
            const int row = rbase + i * 64;
            const uint32_t d = swz((uint32_t)(row * 128 + k16 * 16));
            cpasync16(st + OFF_B0 + d, Bh + (size_t)(bn + row) * EMBED + kofs);
        }
    };

    // prologue: stages 0,1,2 in flight
    issue(0, 0); CP_COMMIT();
    issue(1, 1); CP_COMMIT();
    issue(2, 2); CP_COMMIT();

    int stage = 0;
#pragma unroll 1
    for (int c = 0; c < NCHUNK; ++c) {
        CP_WAIT2();              // group c retired; c+1, c+2 may be in flight
        __syncthreads();         // all warps done reading the stage being overwritten
        if (c + 3 < NCHUNK) issue(c + 3, (stage + 3) & 3);
        CP_COMMIT();             // always commit (keeps group counting sound)

        const uint32_t st = sb + (uint32_t)stage * STAGE_BYTES;
#pragma unroll
        for (int ks = 0; ks < 4; ++ks) {
            uint32_t b0[NNF * 2];
#pragma unroll
            for (int np = 0; np < NNF / 2; ++np) {
                const int rB = wn * WNH + np * 16 + (lane & 7) + ((lane >> 4) & 1) * 8;
                const uint32_t off = swz((uint32_t)(rB * 128 + ks * 32 + ((lane >> 3) & 1) * 16));
                ldsm4(b0[np * 4 + 0], b0[np * 4 + 1], b0[np * 4 + 2], b0[np * 4 + 3],
                      st + OFF_B0 + off);
            }
#pragma unroll
            for (int mf = 0; mf < NMF; ++mf) {
                const int rA = wm * WMH + mf * 16 + (lane & 15);
                const uint32_t off = swz((uint32_t)(rA * 128 + ks * 32 + (lane >> 4) * 16));
                uint32_t a0[4];
                ldsm4(a0[0], a0[1], a0[2], a0[3], st + OFF_A0 + off);
#pragma unroll
                for (int nf = 0; nf < NNF; ++nf)
                    mma16816(acc[mf][nf], a0, &b0[(nf >> 1) * 4 + (nf & 1) * 2]);
            }
        }
        stage = (stage + 1) & 3;
    }

    // ---- epilogue ----
    if (MODE == 0) {
        constexpr float INV = 1.0f / 256.0f;
#pragma unroll
        for (int nf = 0; nf < NNF; ++nf) {
            const int col = bn + wn * WNH + nf * 8 + (lane & 3) * 2;
            const float b0 = bias[col], b1 = bias[col + 1];
#pragma unroll
            for (int mf = 0; mf < NMF; ++mf) {
                const int row = bm + wm * WMH + mf * 16 + (lane >> 2);
                float2 v0 = make_float2(acc[mf][nf][0] * INV + b0, acc[mf][nf][1] * INV + b1);
                float2 v1 = make_float2(acc[mf][nf][2] * INV + b0, acc[mf][nf][3] * INV + b1);
                *reinterpret_cast<float2*>(out + (size_t)row * OUTF + col)       = v0;
                *reinterpret_cast<float2*>(out + (size_t)(row + 8) * OUTF + col) = v1;
            }
        }
    } else {
        const float s = scales[bm >> 10] * 256.0f;
#pragma unroll
        for (int nf = 0; nf < NNF; ++nf) {
            const int col = bn + wn * WNH + nf * 8 + (lane & 3) * 2;
#pragma unroll
            for (int mf = 0; mf < NMF; ++mf) {
                const int row = bm + wm * WMH + mf * 16 + (lane >> 2);
                uint32_t p0 = pack2(__float2half_rn(acc[mf][nf][0] * s),
                                    __float2half_rn(acc[mf][nf][1] * s));
                uint32_t p1 = pack2(__float2half_rn(acc[mf][nf][2] * s),
                                    __float2half_rn(acc[mf][nf][3] * s));
                *reinterpret_cast<uint32_t*>(g_Wh + (size_t)row * EMBED + col)       = p0;
                *reinterpret_cast<uint32_t*>(g_Wh + (size_t)(row + 8) * EMBED + col) = p1;
            }
        }
    }
}

// ---------------------------------------------------------------------------
// Launch. Inputs: x, codewords, indices, rotations, scales, bias.
// ---------------------------------------------------------------------------
extern "C" void kernel_launch(void* const* d_in, const int* in_sizes, int n_in,
                              void* d_out, int out_size)
{
    const float* x         = (const float*)d_in[0];
    const float* codewords = (const float*)d_in[1];
    const int*   indices   = (const int*)  d_in[2];
    const float* rotations = (const float*)d_in[3];
    const float* scales    = (const float*)d_in[4];
    const float* bias      = (const float*)d_in[5];
    float*       out       = (float*)d_out;

    const int M = in_sizes[0] / EMBED;   // 8192

    cudaFuncSetAttribute(gemm_kernel<0>, cudaFuncAttributeMaxDynamicSharedMemorySize, SMEM_DYN);
    cudaFuncSetAttribute(gemm_kernel<1>, cudaFuncAttributeMaxDynamicSharedMemorySize, SMEM_DYN);

    // prep
    conv_x_kernel<<<(size_t)M * EMBED / 4096, NT>>>(x);
    gather_kernel<<<NTILES * RPT, NT>>>(codewords, indices);
    transpose_kernel<<<dim3(EMBED / 128, EMBED / 32, NTILES), NT>>>(rotations);

    // decode: W[4096 x 4096] = cw @ R^T, stored *256 fp16
    gemm_kernel<1><<<dim3(EMBED / 256, (NTILES * RPT) / 128), NTG, SMEM_DYN>>>(
        nullptr, nullptr, scales);

    // linear: out[8192 x 4096] = x @ (W*256)^T / 256 + bias
    gemm_kernel<0><<<dim3(OUTF / 128, M / 256), NTG, SMEM_DYN>>>(
        bias, out, nullptr);
}

// round 9
// speedup vs baseline: 8.3922x; 1.0721x over previous
#include <cuda_runtime.h>
#include <cuda_fp16.h>
#include <cstdint>
#include <cstddef>

// ---------------- problem constants ----------------
#define EMBED   4096
#define RPT     1024
#define NTILES  4
#define OUTF    4096
#define MTOK    8192            // B*S tokens

// ---------------- GEMM tiling ----------------
#define BK 64                   // 64 fp16 = 128B rows -> SW128 swizzle
#define NCHUNK (EMBED / BK)     // 64
#define NTG 256                 // GEMM threads (8 warps)
#define NT  256                 // prep threads
#define NSTAGE 3
#define BMc 128
#define BNc 128
#define STAGE_BYTES ((uint32_t)(BMc + BNc) * 128)   // 32KB
#define SMEM_DYN (NSTAGE * STAGE_BYTES + 1024)      // ~97KB -> 2 CTAs/SM

// warp layout: 8 warps = 2 (M) x 4 (N); warp tile 64x32
#define NMF 4
#define NNF 4
#define WMH 64
#define WNH 32

// ---------------- device scratch (fp16) ----------------
__device__ __half g_Xh[(size_t)MTOK * EMBED];             // x rounded fp16 (64MB)
__device__ __half g_Ah[(size_t)OUTF * EMBED];             // gathered cw fp16 (32MB)
__device__ __half g_Rh[(size_t)NTILES * EMBED * EMBED];   // R^T single fp16 (128MB)
__device__ __half g_Wh[(size_t)OUTF * EMBED];             // decoded W*256 fp16 (32MB)

// ---------------- helpers ----------------
__device__ __forceinline__ uint32_t smem_u32(const void* p) {
    uint32_t a;
    asm("{ .reg .u64 t; cvta.to.shared.u64 t, %1; cvt.u32.u64 %0, t; }" : "=r"(a) : "l"(p));
    return a;
}
__device__ __forceinline__ uint32_t swz(uint32_t b) { return b ^ ((b >> 3) & 0x70); }

__device__ __forceinline__ void ldsm4(uint32_t& r0, uint32_t& r1, uint32_t& r2, uint32_t& r3,
                                      uint32_t addr) {
    asm volatile("ldmatrix.sync.aligned.m8n8.x4.shared.b16 {%0,%1,%2,%3}, [%4];"
                 : "=r"(r0), "=r"(r1), "=r"(r2), "=r"(r3) : "r"(addr));
}
__device__ __forceinline__ void mma16816(float* c, const uint32_t* a, const uint32_t* b) {
    asm volatile(
        "mma.sync.aligned.m16n8k16.row.col.f32.f16.f16.f32 "
        "{%0,%1,%2,%3}, {%4,%5,%6,%7}, {%8,%9}, {%0,%1,%2,%3};"
        : "+f"(c[0]), "+f"(c[1]), "+f"(c[2]), "+f"(c[3])
        : "r"(a[0]), "r"(a[1]), "r"(a[2]), "r"(a[3]), "r"(b[0]), "r"(b[1]));
}
__device__ __forceinline__ void cpasync16(uint32_t dst, const void* src) {
    uint64_t g;
    asm("cvta.to.global.u64 %0, %1;" : "=l"(g) : "l"(src));
    asm volatile("cp.async.cg.shared.global [%0], [%1], 16;" :: "r"(dst), "l"(g));
}
#define CP_COMMIT() asm volatile("cp.async.commit_group;" ::: "memory")
#define CP_WAIT1()  asm volatile("cp.async.wait_group 1;" ::: "memory")

__device__ __forceinline__ uint32_t pack2(__half a, __half b) {
    return (uint32_t)__half_as_ushort(a) | ((uint32_t)__half_as_ushort(b) << 16);
}
__device__ __forceinline__ bool indices_are_i64(const int* __restrict__ p) {
    bool is64 = true;
#pragma unroll
    for (int i = 0; i < 8; ++i) is64 = is64 && (p[2 * i + 1] == 0);
    return is64;
}

// ---------------------------------------------------------------------------
// Prep 1: x -> g_Xh (single fp16)
// ---------------------------------------------------------------------------
__global__ __launch_bounds__(NT)
void conv_x_kernel(const float* __restrict__ x)
{
#pragma unroll
    for (int j = 0; j < 4; ++j) {
        size_t f4 = (size_t)blockIdx.x * 1024 + threadIdx.x + j * 256;
        float4 v = *reinterpret_cast<const float4*>(x + f4 * 4);
        uint2 h;
        h.x = pack2(__float2half_rn(v.x), __float2half_rn(v.y));
        h.y = pack2(__float2half_rn(v.z), __float2half_rn(v.w));
        *reinterpret_cast<uint2*>(g_Xh + f4 * 4) = h;
    }
}

// ---------------------------------------------------------------------------
// Prep 2: gather + round codewords -> g_Ah (single fp16)
// ---------------------------------------------------------------------------
__global__ __launch_bounds__(NT)
void gather_kernel(const float* __restrict__ codewords,
                   const int*   __restrict__ idx_raw)
{
    const int b = blockIdx.x;
    const bool is64 = indices_are_i64(idx_raw);
    const int cidx = is64 ? idx_raw[2 * b] : idx_raw[b];
    const float* __restrict__ src = codewords + (size_t)cidx * EMBED;
#pragma unroll
    for (int j = 0; j < 4; ++j) {
        int e4 = threadIdx.x + j * 256;
        float4 v = *reinterpret_cast<const float4*>(src + e4 * 4);
        uint2 h;
        h.x = pack2(__float2half_rn(v.x), __float2half_rn(v.y));
        h.y = pack2(__float2half_rn(v.z), __float2half_rn(v.w));
        *reinterpret_cast<uint2*>(g_Ah + (size_t)b * EMBED + e4 * 4) = h;
    }
}

// ---------------------------------------------------------------------------
// Prep 3: transpose rotations: R[t][d][e] -> g_Rh [t][e][d] single fp16
// 16B vectorized global writes; conflict-free smem reads (133-float pitch).
// ---------------------------------------------------------------------------
__global__ __launch_bounds__(NT)
void transpose_kernel(const float* __restrict__ rot)
{
    __shared__ float sm[32][133];
    const int xb = blockIdx.x;   // e block (128)
    const int yb = blockIdx.y;   // d block (32)
    const int t  = blockIdx.z;
    const int tid = threadIdx.x;

    // read 32 d-rows x 128 e (coalesced float4), scalar smem stores
#pragma unroll
    for (int p = 0; p < 4; ++p) {
        int dd = p * 8 + (tid >> 5);
        int e4 = (tid & 31);
        float4 v = *reinterpret_cast<const float4*>(
            rot + ((size_t)t * EMBED + yb * 32 + dd) * EMBED + xb * 128 + e4 * 4);
        sm[dd][e4 * 4 + 0] = v.x;
        sm[dd][e4 * 4 + 1] = v.y;
        sm[dd][e4 * 4 + 2] = v.z;
        sm[dd][e4 * 4 + 3] = v.w;
    }
    __syncthreads();

    // write: thread -> (e, 8 consecutive d) = 16B store
    const int dg = tid & 3;          // d group (8 d's each)
#pragma unroll
    for (int p = 0; p < 2; ++p) {
        int e = (tid >> 2) + p * 64;
        uint4 w;
        uint32_t* wp = reinterpret_cast<uint32_t*>(&w);
#pragma unroll
        for (int j = 0; j < 4; ++j) {
            float f0 = sm[dg * 8 + 2 * j][e];
            float f1 = sm[dg * 8 + 2 * j + 1][e];
            wp[j] = pack2(__float2half_rn(f0), __float2half_rn(f1));
        }
        size_t o = (size_t)t * EMBED * EMBED + (size_t)(xb * 128 + e) * EMBED
                 + yb * 32 + dg * 8;
        *reinterpret_cast<uint4*>(g_Rh + o) = w;
    }
}

// ---------------------------------------------------------------------------
// Single-term fp16 GEMM, 256 threads (8 warps), CTA 128x128, warp 64x32,
// 3-stage cp.async pipeline, 2 CTAs/SM.
// MODE 0 (linear): A = Xh, B = Wh. out = C/256 + bias
// MODE 1 (decode): A = Ah, B = Rh[tile]. g_Wh = fp16(C * scales[t] * 256)
// ---------------------------------------------------------------------------
template<int MODE>
__global__ __launch_bounds__(NTG, 2)
void gemm_kernel(const float* __restrict__ bias, float* __restrict__ out,
                 const float* __restrict__ scales)
{
    constexpr uint32_t OFF_A0 = 0;
    constexpr uint32_t OFF_B0 = (uint32_t)BMc * 128;

    extern __shared__ char smraw[];
    const uint32_t sraw = smem_u32(smraw);
    const uint32_t sb   = (sraw + 1023u) & ~1023u;

    const int tid  = threadIdx.x;
    const int wid  = tid >> 5;
    const int lane = tid & 31;
    const int wm   = wid & 1;        // 2 warps along M
    const int wn   = wid >> 1;       // 4 warps along N
    const int bm   = blockIdx.y * BMc;
    const int bn   = blockIdx.x * BNc;

    const __half* __restrict__ Ah = (MODE == 1) ? g_Ah : g_Xh;
    const __half* __restrict__ Bh = (MODE == 1)
        ? g_Rh + (size_t)(bm >> 10) * EMBED * EMBED : g_Wh;

    const int k16   = tid & 7;      // 16B column within 128B row
    const int rbase = tid >> 3;     // 0..31

    float acc[NMF][NNF][4];
#pragma unroll
    for (int i = 0; i < NMF; ++i)
#pragma unroll
        for (int j = 0; j < NNF; ++j)
#pragma unroll
            for (int q = 0; q < 4; ++q) acc[i][j][q] = 0.0f;

    auto issue = [&](int c, int stage) {
        const uint32_t st = sb + (uint32_t)stage * STAGE_BYTES;
        const size_t kofs = (size_t)c * BK + k16 * 8;
#pragma unroll
        for (int i = 0; i < BMc / 32; ++i) {
            const int row = rbase + i * 32;
            const uint32_t d = swz((uint32_t)(row * 128 + k16 * 16));
            cpasync16(st + OFF_A0 + d, Ah + (size_t)(bm + row) * EMBED + kofs);
        }
#pragma unroll
        for (int i = 0; i < BNc / 32; ++i) {
            const int row = rbase + i * 32;
            const uint32_t d = swz((uint32_t)(row * 128 + k16 * 16));
            cpasync16(st + OFF_B0 + d, Bh + (size_t)(bn + row) * EMBED + kofs);
        }
    };

    // prologue: stages 0,1 in flight
    issue(0, 0); CP_COMMIT();
    issue(1, 1); CP_COMMIT();

    int stage = 0;
#pragma unroll 1
    for (int c = 0; c < NCHUNK; ++c) {
        CP_WAIT1();              // group c retired; c+1 may be in flight
        __syncthreads();         // all warps done reading the stage being overwritten
        if (c + 2 < NCHUNK) issue(c + 2, (stage + 2) % NSTAGE);
        CP_COMMIT();             // always commit (keeps group counting sound)

        const uint32_t st = sb + (uint32_t)stage * STAGE_BYTES;
#pragma unroll
        for (int ks = 0; ks < 4; ++ks) {
            uint32_t b0[NNF * 2];
#pragma unroll
            for (int np = 0; np < NNF / 2; ++np) {
                const int rB = wn * WNH + np * 16 + (lane & 7) + ((lane >> 4) & 1) * 8;
                const uint32_t off = swz((uint32_t)(rB * 128 + ks * 32 + ((lane >> 3) & 1) * 16));
                ldsm4(b0[np * 4 + 0], b0[np * 4 + 1], b0[np * 4 + 2], b0[np * 4 + 3],
                      st + OFF_B0 + off);
            }
#pragma unroll
            for (int mf = 0; mf < NMF; ++mf) {
                const int rA = wm * WMH + mf * 16 + (lane & 15);
                const uint32_t off = swz((uint32_t)(rA * 128 + ks * 32 + (lane >> 4) * 16));
                uint32_t a0[4];
                ldsm4(a0[0], a0[1], a0[2], a0[3], st + OFF_A0 + off);
#pragma unroll
                for (int nf = 0; nf < NNF; ++nf)
                    mma16816(acc[mf][nf], a0, &b0[(nf >> 1) * 4 + (nf & 1) * 2]);
            }
        }
        stage = (stage + 1) % NSTAGE;
    }

    // ---- epilogue ----
    if (MODE == 0) {
        constexpr float INV = 1.0f / 256.0f;
#pragma unroll
        for (int nf = 0; nf < NNF; ++nf) {
            const int col = bn + wn * WNH + nf * 8 + (lane & 3) * 2;
            const float b0 = bias[col], b1 = bias[col + 1];
#pragma unroll
            for (int mf = 0; mf < NMF; ++mf) {
                const int row = bm + wm * WMH + mf * 16 + (lane >> 2);
                float2 v0 = make_float2(acc[mf][nf][0] * INV + b0, acc[mf][nf][1] * INV + b1);
                float2 v1 = make_float2(acc[mf][nf][2] * INV + b0, acc[mf][nf][3] * INV + b1);
                *reinterpret_cast<float2*>(out + (size_t)row * OUTF + col)       = v0;
                *reinterpret_cast<float2*>(out + (size_t)(row + 8) * OUTF + col) = v1;
            }
        }
    } else {
        const float s = scales[bm >> 10] * 256.0f;
#pragma unroll
        for (int nf = 0; nf < NNF; ++nf) {
            const int col = bn + wn * WNH + nf * 8 + (lane & 3) * 2;
#pragma unroll
            for (int mf = 0; mf < NMF; ++mf) {
                const int row = bm + wm * WMH + mf * 16 + (lane >> 2);
                uint32_t p0 = pack2(__float2half_rn(acc[mf][nf][0] * s),
                                    __float2half_rn(acc[mf][nf][1] * s));
                uint32_t p1 = pack2(__float2half_rn(acc[mf][nf][2] * s),
                                    __float2half_rn(acc[mf][nf][3] * s));
                *reinterpret_cast<uint32_t*>(g_Wh + (size_t)row * EMBED + col)       = p0;
                *reinterpret_cast<uint32_t*>(g_Wh + (size_t)(row + 8) * EMBED + col) = p1;
            }
        }
    }
}

// ---------------------------------------------------------------------------
// Launch. Inputs: x, codewords, indices, rotations, scales, bias.
// ---------------------------------------------------------------------------
extern "C" void kernel_launch(void* const* d_in, const int* in_sizes, int n_in,
                              void* d_out, int out_size)
{
    const float* x         = (const float*)d_in[0];
    const float* codewords = (const float*)d_in[1];
    const int*   indices   = (const int*)  d_in[2];
    const float* rotations = (const float*)d_in[3];
    const float* scales    = (const float*)d_in[4];
    const float* bias      = (const float*)d_in[5];
    float*       out       = (float*)d_out;

    const int M = in_sizes[0] / EMBED;   // 8192

    cudaFuncSetAttribute(gemm_kernel<0>, cudaFuncAttributeMaxDynamicSharedMemorySize, SMEM_DYN);
    cudaFuncSetAttribute(gemm_kernel<1>, cudaFuncAttributeMaxDynamicSharedMemorySize, SMEM_DYN);

    // prep
    conv_x_kernel<<<(size_t)M * EMBED / 4096, NT>>>(x);
    gather_kernel<<<NTILES * RPT, NT>>>(codewords, indices);
    transpose_kernel<<<dim3(EMBED / 128, EMBED / 32, NTILES), NT>>>(rotations);

    // decode: W[4096 x 4096] = cw @ R^T, stored *256 fp16
    gemm_kernel<1><<<dim3(EMBED / BNc, (NTILES * RPT) / BMc), NTG, SMEM_DYN>>>(
        nullptr, nullptr, scales);

    // linear: out[8192 x 4096] = x @ (W*256)^T / 256 + bias
    gemm_kernel<0><<<dim3(OUTF / BNc, M / BMc), NTG, SMEM_DYN>>>(
        bias, out, nullptr);
}

// round 10
// speedup vs baseline: 8.9090x; 1.0616x over previous
#include <cuda_runtime.h>
#include <cuda_fp16.h>
#include <cstdint>
#include <cstddef>

// ---------------- problem constants ----------------
#define EMBED   4096
#define RPT     1024
#define NTILES  4
#define OUTF    4096
#define MTOK    8192            // B*S tokens

// ---------------- GEMM tiling ----------------
#define BK 64                   // 64 fp16 = 128B rows -> SW128 swizzle
#define NCHUNK (EMBED / BK)     // 64
#define NTG 128                 // GEMM threads (4 warps)
#define NT  256                 // prep threads
#define NSTAGE 3
#define BMc 128
#define BNc 128
#define STAGE_BYTES ((uint32_t)(BMc + BNc) * 128)   // 32KB
#define SMEM_DYN (NSTAGE * STAGE_BYTES + 1024)      // ~97KB -> 2 CTAs/SM

// warp layout: 4 warps = 2 (M) x 2 (N); warp tile 64x64
#define NMF 4
#define NNF 8
#define WMH 64
#define WNH 64

// ---------------- device scratch (fp16) ----------------
__device__ __half g_Xh[(size_t)MTOK * EMBED];             // x rounded fp16 (64MB)
__device__ __half g_Ah[(size_t)OUTF * EMBED];             // gathered cw fp16 (32MB)
__device__ __half g_Rh[(size_t)NTILES * EMBED * EMBED];   // R^T single fp16 (128MB)
__device__ __half g_Wh[(size_t)OUTF * EMBED];             // decoded W*256 fp16 (32MB)

// ---------------- helpers ----------------
__device__ __forceinline__ uint32_t smem_u32(const void* p) {
    uint32_t a;
    asm("{ .reg .u64 t; cvta.to.shared.u64 t, %1; cvt.u32.u64 %0, t; }" : "=r"(a) : "l"(p));
    return a;
}
__device__ __forceinline__ uint32_t swz(uint32_t b) { return b ^ ((b >> 3) & 0x70); }

__device__ __forceinline__ void ldsm4(uint32_t& r0, uint32_t& r1, uint32_t& r2, uint32_t& r3,
                                      uint32_t addr) {
    asm volatile("ldmatrix.sync.aligned.m8n8.x4.shared.b16 {%0,%1,%2,%3}, [%4];"
                 : "=r"(r0), "=r"(r1), "=r"(r2), "=r"(r3) : "r"(addr));
}
__device__ __forceinline__ void mma16816(float* c, const uint32_t* a, const uint32_t* b) {
    asm volatile(
        "mma.sync.aligned.m16n8k16.row.col.f32.f16.f16.f32 "
        "{%0,%1,%2,%3}, {%4,%5,%6,%7}, {%8,%9}, {%0,%1,%2,%3};"
        : "+f"(c[0]), "+f"(c[1]), "+f"(c[2]), "+f"(c[3])
        : "r"(a[0]), "r"(a[1]), "r"(a[2]), "r"(a[3]), "r"(b[0]), "r"(b[1]));
}
__device__ __forceinline__ void cpasync16(uint32_t dst, const void* src) {
    uint64_t g;
    asm("cvta.to.global.u64 %0, %1;" : "=l"(g) : "l"(src));
    asm volatile("cp.async.cg.shared.global [%0], [%1], 16;" :: "r"(dst), "l"(g));
}
#define CP_COMMIT() asm volatile("cp.async.commit_group;" ::: "memory")
#define CP_WAIT1()  asm volatile("cp.async.wait_group 1;" ::: "memory")

__device__ __forceinline__ uint32_t pack2(__half a, __half b) {
    return (uint32_t)__half_as_ushort(a) | ((uint32_t)__half_as_ushort(b) << 16);
}
__device__ __forceinline__ bool indices_are_i64(const int* __restrict__ p) {
    bool is64 = true;
#pragma unroll
    for (int i = 0; i < 8; ++i) is64 = is64 && (p[2 * i + 1] == 0);
    return is64;
}

// ---------------------------------------------------------------------------
// Prep 1: x -> g_Xh (single fp16)
// ---------------------------------------------------------------------------
__global__ __launch_bounds__(NT)
void conv_x_kernel(const float* __restrict__ x)
{
#pragma unroll
    for (int j = 0; j < 4; ++j) {
        size_t f4 = (size_t)blockIdx.x * 1024 + threadIdx.x + j * 256;
        float4 v = *reinterpret_cast<const float4*>(x + f4 * 4);
        uint2 h;
        h.x = pack2(__float2half_rn(v.x), __float2half_rn(v.y));
        h.y = pack2(__float2half_rn(v.z), __float2half_rn(v.w));
        *reinterpret_cast<uint2*>(g_Xh + f4 * 4) = h;
    }
}

// ---------------------------------------------------------------------------
// Prep 2: gather + round codewords -> g_Ah (single fp16)
// ---------------------------------------------------------------------------
__global__ __launch_bounds__(NT)
void gather_kernel(const float* __restrict__ codewords,
                   const int*   __restrict__ idx_raw)
{
    const int b = blockIdx.x;
    const bool is64 = indices_are_i64(idx_raw);
    const int cidx = is64 ? idx_raw[2 * b] : idx_raw[b];
    const float* __restrict__ src = codewords + (size_t)cidx * EMBED;
#pragma unroll
    for (int j = 0; j < 4; ++j) {
        int e4 = threadIdx.x + j * 256;
        float4 v = *reinterpret_cast<const float4*>(src + e4 * 4);
        uint2 h;
        h.x = pack2(__float2half_rn(v.x), __float2half_rn(v.y));
        h.y = pack2(__float2half_rn(v.z), __float2half_rn(v.w));
        *reinterpret_cast<uint2*>(g_Ah + (size_t)b * EMBED + e4 * 4) = h;
    }
}

// ---------------------------------------------------------------------------
// Prep 3: transpose rotations: R[t][d][e] -> g_Rh [t][e][d] single fp16
// ---------------------------------------------------------------------------
__global__ __launch_bounds__(NT)
void transpose_kernel(const float* __restrict__ rot)
{
    __shared__ float sm[32][133];
    const int xb = blockIdx.x;   // e block (128)
    const int yb = blockIdx.y;   // d block (32)
    const int t  = blockIdx.z;
    const int tid = threadIdx.x;

#pragma unroll
    for (int p = 0; p < 4; ++p) {
        int dd = p * 8 + (tid >> 5);
        int e4 = (tid & 31);
        float4 v = *reinterpret_cast<const float4*>(
            rot + ((size_t)t * EMBED + yb * 32 + dd) * EMBED + xb * 128 + e4 * 4);
        sm[dd][e4 * 4 + 0] = v.x;
        sm[dd][e4 * 4 + 1] = v.y;
        sm[dd][e4 * 4 + 2] = v.z;
        sm[dd][e4 * 4 + 3] = v.w;
    }
    __syncthreads();

    const int dg = tid & 3;          // d group (8 d's each)
#pragma unroll
    for (int p = 0; p < 2; ++p) {
        int e = (tid >> 2) + p * 64;
        uint4 w;
        uint32_t* wp = reinterpret_cast<uint32_t*>(&w);
#pragma unroll
        for (int j = 0; j < 4; ++j) {
            float f0 = sm[dg * 8 + 2 * j][e];
            float f1 = sm[dg * 8 + 2 * j + 1][e];
            wp[j] = pack2(__float2half_rn(f0), __float2half_rn(f1));
        }
        size_t o = (size_t)t * EMBED * EMBED + (size_t)(xb * 128 + e) * EMBED
                 + yb * 32 + dg * 8;
        *reinterpret_cast<uint4*>(g_Rh + o) = w;
    }
}

// ---------------------------------------------------------------------------
// Single-term fp16 GEMM, 128 threads (4 warps 2x2), warp tile 64x64,
// CTA 128x128, 3-stage cp.async pipeline, 2 CTAs/SM.
// MODE 0 (linear): A = Xh, B = Wh. out = C/256 + bias
// MODE 1 (decode): A = Ah, B = Rh[tile]. g_Wh = fp16(C * scales[t] * 256)
// ---------------------------------------------------------------------------
template<int MODE>
__global__ __launch_bounds__(NTG, 2)
void gemm_kernel(const float* __restrict__ bias, float* __restrict__ out,
                 const float* __restrict__ scales)
{
    constexpr uint32_t OFF_A0 = 0;
    constexpr uint32_t OFF_B0 = (uint32_t)BMc * 128;

    extern __shared__ char smraw[];
    const uint32_t sraw = smem_u32(smraw);
    const uint32_t sb   = (sraw + 1023u) & ~1023u;

    const int tid  = threadIdx.x;
    const int wid  = tid >> 5;
    const int lane = tid & 31;
    const int wm   = wid & 1;        // 2 warps along M
    const int wn   = wid >> 1;       // 2 warps along N
    const int bm   = blockIdx.y * BMc;
    const int bn   = blockIdx.x * BNc;

    const __half* __restrict__ Ah = (MODE == 1) ? g_Ah : g_Xh;
    const __half* __restrict__ Bh = (MODE == 1)
        ? g_Rh + (size_t)(bm >> 10) * EMBED * EMBED : g_Wh;

    const int k16   = tid & 7;      // 16B column within 128B row
    const int rbase = tid >> 3;     // 0..15

    float acc[NMF][NNF][4];
#pragma unroll
    for (int i = 0; i < NMF; ++i)
#pragma unroll
        for (int j = 0; j < NNF; ++j)
#pragma unroll
            for (int q = 0; q < 4; ++q) acc[i][j][q] = 0.0f;

    auto issue = [&](int c, int stage) {
        const uint32_t st = sb + (uint32_t)stage * STAGE_BYTES;
        const size_t kofs = (size_t)c * BK + k16 * 8;
#pragma unroll
        for (int i = 0; i < BMc / 16; ++i) {
            const int row = rbase + i * 16;
            const uint32_t d = swz((uint32_t)(row * 128 + k16 * 16));
            cpasync16(st + OFF_A0 + d, Ah + (size_t)(bm + row) * EMBED + kofs);
        }
#pragma unroll
        for (int i = 0; i < BNc / 16; ++i) {
            const int row = rbase + i * 16;
            const uint32_t d = swz((uint32_t)(row * 128 + k16 * 16));
            cpasync16(st + OFF_B0 + d, Bh + (size_t)(bn + row) * EMBED + kofs);
        }
    };

    // prologue: stages 0,1 in flight
    issue(0, 0); CP_COMMIT();
    issue(1, 1); CP_COMMIT();

    int stage = 0;
#pragma unroll 1
    for (int c = 0; c < NCHUNK; ++c) {
        CP_WAIT1();              // group c retired; c+1 may be in flight
        __syncthreads();         // all warps done reading the stage being overwritten
        if (c + 2 < NCHUNK) issue(c + 2, (stage + 2) % NSTAGE);
        CP_COMMIT();             // always commit (keeps group counting sound)

        const uint32_t st = sb + (uint32_t)stage * STAGE_BYTES;
#pragma unroll
        for (int ks = 0; ks < 4; ++ks) {
            uint32_t b0[NNF * 2];
#pragma unroll
            for (int np = 0; np < NNF / 2; ++np) {
                const int rB = wn * WNH + np * 16 + (lane & 7) + ((lane >> 4) & 1) * 8;
                const uint32_t off = swz((uint32_t)(rB * 128 + ks * 32 + ((lane >> 3) & 1) * 16));
                ldsm4(b0[np * 4 + 0], b0[np * 4 + 1], b0[np * 4 + 2], b0[np * 4 + 3],
                      st + OFF_B0 + off);
            }
#pragma unroll
            for (int mf = 0; mf < NMF; ++mf) {
                const int rA = wm * WMH + mf * 16 + (lane & 15);
                const uint32_t off = swz((uint32_t)(rA * 128 + ks * 32 + (lane >> 4) * 16));
                uint32_t a0[4];
                ldsm4(a0[0], a0[1], a0[2], a0[3], st + OFF_A0 + off);
#pragma unroll
                for (int nf = 0; nf < NNF; ++nf)
                    mma16816(acc[mf][nf], a0, &b0[(nf >> 1) * 4 + (nf & 1) * 2]);
            }
        }
        stage = (stage + 1) % NSTAGE;
    }

    // ---- epilogue ----
    if (MODE == 0) {
        constexpr float INV = 1.0f / 256.0f;
#pragma unroll
        for (int nf = 0; nf < NNF; ++nf) {
            const int col = bn + wn * WNH + nf * 8 + (lane & 3) * 2;
            const float b0 = bias[col], b1 = bias[col + 1];
#pragma unroll
            for (int mf = 0; mf < NMF; ++mf) {
                const int row = bm + wm * WMH + mf * 16 + (lane >> 2);
                float2 v0 = make_float2(acc[mf][nf][0] * INV + b0, acc[mf][nf][1] * INV + b1);
                float2 v1 = make_float2(acc[mf][nf][2] * INV + b0, acc[mf][nf][3] * INV + b1);
                *reinterpret_cast<float2*>(out + (size_t)row * OUTF + col)       = v0;
                *reinterpret_cast<float2*>(out + (size_t)(row + 8) * OUTF + col) = v1;
            }
        }
    } else {
        const float s = scales[bm >> 10] * 256.0f;
#pragma unroll
        for (int nf = 0; nf < NNF; ++nf) {
            const int col = bn + wn * WNH + nf * 8 + (lane & 3) * 2;
#pragma unroll
            for (int mf = 0; mf < NMF; ++mf) {
                const int row = bm + wm * WMH + mf * 16 + (lane >> 2);
                uint32_t p0 = pack2(__float2half_rn(acc[mf][nf][0] * s),
                                    __float2half_rn(acc[mf][nf][1] * s));
                uint32_t p1 = pack2(__float2half_rn(acc[mf][nf][2] * s),
                                    __float2half_rn(acc[mf][nf][3] * s));
                *reinterpret_cast<uint32_t*>(g_Wh + (size_t)row * EMBED + col)       = p0;
                *reinterpret_cast<uint32_t*>(g_Wh + (size_t)(row + 8) * EMBED + col) = p1;
            }
        }
    }
}

// ---------------------------------------------------------------------------
// Launch. Inputs: x, codewords, indices, rotations, scales, bias.
// ---------------------------------------------------------------------------
extern "C" void kernel_launch(void* const* d_in, const int* in_sizes, int n_in,
                              void* d_out, int out_size)
{
    const float* x         = (const float*)d_in[0];
    const float* codewords = (const float*)d_in[1];
    const int*   indices   = (const int*)  d_in[2];
    const float* rotations = (const float*)d_in[3];
    const float* scales    = (const float*)d_in[4];
    const float* bias      = (const float*)d_in[5];
    float*       out       = (float*)d_out;

    const int M = in_sizes[0] / EMBED;   // 8192

    cudaFuncSetAttribute(gemm_kernel<0>, cudaFuncAttributeMaxDynamicSharedMemorySize, SMEM_DYN);
    cudaFuncSetAttribute(gemm_kernel<1>, cudaFuncAttributeMaxDynamicSharedMemorySize, SMEM_DYN);

    // prep
    conv_x_kernel<<<(size_t)M * EMBED / 4096, NT>>>(x);
    gather_kernel<<<NTILES * RPT, NT>>>(codewords, indices);
    transpose_kernel<<<dim3(EMBED / 128, EMBED / 32, NTILES), NT>>>(rotations);

    // decode: W[4096 x 4096] = cw @ R^T, stored *256 fp16
    gemm_kernel<1><<<dim3(EMBED / BNc, (NTILES * RPT) / BMc), NTG, SMEM_DYN>>>(
        nullptr, nullptr, scales);

    // linear: out[8192 x 4096] = x @ (W*256)^T / 256 + bias
    gemm_kernel<0><<<dim3(OUTF / BNc, M / BMc), NTG, SMEM_DYN>>>(
        bias, out, nullptr);
}